// round 10
// baseline (speedup 1.0000x reference)
#include <cuda_runtime.h>

#define N_NODES 20000
#define N_EDGES 60000
#define NODE_IN 8
#define HID     64
#define BATCH   256
#define MLP_H   128
#define N_ACT   20000

typedef unsigned long long ULL;

// ---------------- device scratch ----------------
__device__ float d_h1e[N_EDGES * HID];
__device__ float d_h2e[N_EDGES * HID];
__device__ float d_deg[N_NODES];
__device__ float d_agg1[N_NODES * HID];
__device__ float d_h1[N_NODES * HID];
__device__ float d_agg2[N_NODES * HID];
__device__ float d_colsum[HID];
__device__ float d_g[HID];
__device__ float d_y1[BATCH * MLP_H];
__device__ float d_z1[BATCH * MLP_H];
__device__ float d_z2[BATCH * MLP_H];
__device__ float d_bn1[N_NODES * HID];
__device__ float d_bn2[N_NODES * HID];
__device__ float d_Mn[(size_t)N_NODES * 4096];   // per-node weight matrices [n][k][o]
// CSR by src
__device__ int d_srccnt[N_NODES];
__device__ int d_fill[N_NODES];
__device__ int d_srcptr[N_NODES + 1];
__device__ int d_elist[N_EDGES];

// f32x2 packed helpers
__device__ __forceinline__ ULL pack2(float v) {
    ULL r;
    asm("mov.b64 %0, {%1, %1};" : "=l"(r) : "f"(v));
    return r;
}
__device__ __forceinline__ void fma2(ULL& acc, ULL a, ULL b) {
    asm("fma.rn.f32x2 %0, %1, %2, %0;" : "+l"(acc) : "l"(a), "l"(b));
}
__device__ __forceinline__ void unpack2(ULL v, float& lo, float& hi) {
    asm("mov.b64 {%0, %1}, %2;" : "=f"(lo), "=f"(hi) : "l"(v));
}

// ---------------- zero scratch ----------------
__global__ void zero_kernel() {
    int i  = blockIdx.x * blockDim.x + threadIdx.x;
    int gs = gridDim.x * blockDim.x;
    for (int j = i; j < N_NODES * HID; j += gs) { d_agg1[j] = 0.f; d_agg2[j] = 0.f; }
    for (int j = i; j < N_NODES; j += gs) { d_deg[j] = 0.f; d_srccnt[j] = 0; d_fill[j] = 0; }
    for (int j = i; j < BATCH * MLP_H; j += gs) d_y1[j] = 0.f;
    if (i < HID) d_colsum[i] = 0.f;
}

// ---------------- per-node bias: bn[n][o] = sum_i xin[n,i]*b2[i*64+o] ----------------
template<int IDIM>
__global__ void bn_kernel(const float* __restrict__ xin_param,
                          const float* __restrict__ b2) {
    const float* xin = (IDIM == 8) ? xin_param : d_h1;
    float* bno = (IDIM == 8) ? d_bn1 : d_bn2;
    __shared__ float b2s[IDIM * 64];
    __shared__ float xs[4][IDIM];
    int tid = threadIdx.x;
    for (int idx = tid; idx < IDIM * 64; idx += 256) b2s[idx] = b2[idx];
    int n0 = blockIdx.x * 4;
    if (tid < 4 * IDIM) {
        int ln = tid / IDIM, i = tid % IDIM;
        int n = n0 + ln;
        xs[ln][i] = (n < N_NODES) ? xin[n * IDIM + i] : 0.f;
    }
    __syncthreads();
    int c = tid & 63, ln = tid >> 6, n = n0 + ln;
    if (n < N_NODES) {
        float s = 0.f;
#pragma unroll 8
        for (int i = 0; i < IDIM; i++) s += xs[ln][i] * b2s[i * 64 + c];
        bno[n * 64 + c] = s;
    }
}

// ---------------- edge feature MLPs + degree counts ----------------
__global__ void edge_feat_kernel(const float* __restrict__ edge_attr,
                                 const int*   __restrict__ edge_index,
                                 const float* __restrict__ W1a, const float* __restrict__ b1a,
                                 const float* __restrict__ W1b, const float* __restrict__ b1b) {
    __shared__ float wa[256], wb[256], ba[64], bb[64], ea[16][4];
    int tid = threadIdx.x;
    wa[tid] = W1a[tid];
    wb[tid] = W1b[tid];
    if (tid < 64) { ba[tid] = b1a[tid]; bb[tid] = b1b[tid]; }
    int e0 = blockIdx.x * 16;
    if (tid < 64) {
        int le = tid >> 2, j = tid & 3;
        int e = e0 + le;
        ea[le][j] = (e < N_EDGES) ? edge_attr[e * 4 + j] : 0.f;
    }
    __syncthreads();
    int c = tid & 63;
#pragma unroll
    for (int ch = 0; ch < 4; ch++) {
        int le = (tid >> 6) + ch * 4;
        int e = e0 + le;
        if (e < N_EDGES) {
            float s1 = ba[c], s2 = bb[c];
#pragma unroll
            for (int j = 0; j < 4; j++) {
                s1 += ea[le][j] * wa[j * 64 + c];
                s2 += ea[le][j] * wb[j * 64 + c];
            }
            d_h1e[e * 64 + c] = fmaxf(s1, 0.f);
            d_h2e[e * 64 + c] = fmaxf(s2, 0.f);
            if (c == 0) atomicAdd(&d_deg[edge_index[N_EDGES + e]], 1.f);
            if (c == 1) atomicAdd(&d_srccnt[edge_index[e]], 1);
        }
    }
}

// ---------------- Mn GEMM: d_Mn[n, k*64+o] = sum_i xin[n,i] * W2[k, i*64+o] ------
// Block: 128 nodes x 128 cols, 256 threads, 8x8 per thread, f32x2 inner loop.
template<int IDIM>
__launch_bounds__(256, 2)
__global__ void mn_gemm(const float* __restrict__ xin_param,
                        const float* __restrict__ W2) {
    const float* xin = (IDIM == 8) ? xin_param : d_h1;
    constexpr int WROW = IDIM * 64;
    constexpr int SR = 132;          // smem row stride (floats)

    extern __shared__ float smg[];
    float* As = smg;                 // [IDIM][SR]  As[i][n]
    float* Bs = As + IDIM * SR;      // [IDIM][SR]  Bs[i][c]

    int tid = threadIdx.x;
    int nb0 = blockIdx.x * 128;
    int cb0 = blockIdx.y * 128;

    // A: transposed node features
    for (int idx = tid; idx < 128 * IDIM; idx += 256) {
        int n = idx / IDIM, i = idx % IDIM;
        int gn = nb0 + n;
        As[i * SR + n] = (gn < N_NODES) ? xin[gn * IDIM + i] : 0.f;
    }
    // B: W2 reindexed — Bs[i][c] = W2[k, i*64+o], k=(cb0+c)>>6, o=(cb0+c)&63
    for (int idx = tid; idx < 128 * IDIM; idx += 256) {
        int i = idx >> 7, c = idx & 127;
        int gc = cb0 + c;
        Bs[i * SR + c] = W2[(gc >> 6) * WROW + i * 64 + (gc & 63)];
    }
    __syncthreads();

    int tc = tid & 15, tn = tid >> 4;
    int c0 = tc * 8, n0 = tn * 8;

    ULL acc[8][4];
#pragma unroll
    for (int a = 0; a < 8; a++)
#pragma unroll
        for (int p = 0; p < 4; p++) acc[a][p] = 0ull;

#pragma unroll 8
    for (int i = 0; i < IDIM; i++) {
        const float4* ar = (const float4*)(As + i * SR + n0);
        float4 xa = ar[0], xb = ar[1];
        ULL h[8];
        h[0] = pack2(xa.x); h[1] = pack2(xa.y); h[2] = pack2(xa.z); h[3] = pack2(xa.w);
        h[4] = pack2(xb.x); h[5] = pack2(xb.y); h[6] = pack2(xb.z); h[7] = pack2(xb.w);
        const ULL* bp = (const ULL*)(Bs + i * SR + c0);
#pragma unroll
        for (int p = 0; p < 4; p++) {
            ULL wv = bp[p];
            fma2(acc[0][p], h[0], wv); fma2(acc[1][p], h[1], wv);
            fma2(acc[2][p], h[2], wv); fma2(acc[3][p], h[3], wv);
            fma2(acc[4][p], h[4], wv); fma2(acc[5][p], h[5], wv);
            fma2(acc[6][p], h[6], wv); fma2(acc[7][p], h[7], wv);
        }
    }
    // store
#pragma unroll
    for (int a = 0; a < 8; a++) {
        int gn = nb0 + n0 + a;
        if (gn < N_NODES) {
            ULL* cp = (ULL*)(d_Mn + (size_t)gn * 4096 + cb0 + c0);
#pragma unroll
            for (int p = 0; p < 4; p++) cp[p] = acc[a][p];
        }
    }
}

// ---------------- exclusive scan of src counts (single block) ----------------
__global__ void scan_kernel() {
    __shared__ int part[512];
    int tid = threadIdx.x;
    const int CH = (N_NODES + 511) / 512;   // 40
    int base = tid * CH;
    int s = 0;
    for (int j = 0; j < CH; j++) {
        int idx = base + j;
        if (idx < N_NODES) s += d_srccnt[idx];
    }
    part[tid] = s;
    __syncthreads();
    for (int off = 1; off < 512; off <<= 1) {
        int v = (tid >= off) ? part[tid - off] : 0;
        __syncthreads();
        part[tid] += v;
        __syncthreads();
    }
    int run = (tid > 0) ? part[tid - 1] : 0;
    for (int j = 0; j < CH; j++) {
        int idx = base + j;
        if (idx < N_NODES) { d_srcptr[idx] = run; run += d_srccnt[idx]; }
    }
    if (tid == 511) d_srcptr[N_NODES] = run;
}

// ---------------- scatter edges into CSR lists ----------------
__global__ void scatter_kernel(const int* __restrict__ edge_index) {
    int e = blockIdx.x * 256 + threadIdx.x;
    if (e < N_EDGES) {
        int s = edge_index[e];
        int pos = d_srcptr[s] + atomicAdd(&d_fill[s], 1);
        d_elist[pos] = e;
    }
}

// ---------------- consume: msg[e] = hE[e] @ Mn[src_e] + bn[src_e] -> agg[dst_e] ----
// One warp per edge; lane l owns outputs (2l, 2l+1). Edges in CSR-by-src order
// so consecutive edges reuse the 16KB Mn row from cache.
template<int LAYER>
__global__ void consume_kernel(const int* __restrict__ edge_index) {
    const float* hE  = (LAYER == 1) ? d_h1e : d_h2e;
    const float* bno = (LAYER == 1) ? d_bn1 : d_bn2;
    float*       agg = (LAYER == 1) ? d_agg1 : d_agg2;
    int w = threadIdx.x >> 5, l = threadIdx.x & 31;
    int base = blockIdx.x * 64 + w * 8;
    for (int j = 0; j < 8; j++) {
        int t = base + j;
        if (t >= N_EDGES) break;
        int e = d_elist[t];
        int s = edge_index[e];
        int d = edge_index[N_EDGES + e];
        float hv0 = hE[e * 64 + l];
        float hv1 = hE[e * 64 + 32 + l];
        const ULL* mp = (const ULL*)(d_Mn + (size_t)s * 4096) + l;
        ULL acc = 0ull;
#pragma unroll
        for (int k = 0; k < 32; k++) {
            float hk = __shfl_sync(0xFFFFFFFFu, hv0, k);
            fma2(acc, pack2(hk), mp[k * 32]);
        }
#pragma unroll
        for (int k = 0; k < 32; k++) {
            float hk = __shfl_sync(0xFFFFFFFFu, hv1, k);
            fma2(acc, pack2(hk), mp[(32 + k) * 32]);
        }
        ULL bnv = ((const ULL*)(bno + s * 64))[l];
        fma2(acc, pack2(1.0f), bnv);
        float a0, a1; unpack2(acc, a0, a1);
        atomicAdd(&agg[d * 64 + 2 * l], a0);
        atomicAdd(&agg[d * 64 + 2 * l + 1], a1);
    }
}

// ---------------- node update 1 ----------------
__global__ void node_update1(const float* __restrict__ x,
                             const float* __restrict__ root1,
                             const float* __restrict__ bias1) {
    __shared__ float r1[512], b1s[64], xs[4][8], dn[4];
    int tid = threadIdx.x;
    r1[tid] = root1[tid];
    r1[tid + 256] = root1[tid + 256];
    if (tid < 64) b1s[tid] = bias1[tid];
    int n0 = blockIdx.x * 4;
    if (tid < 32) {
        int ln = tid >> 3, j = tid & 7;
        int n = n0 + ln;
        xs[ln][j] = (n < N_NODES) ? x[n * 8 + j] : 0.f;
    }
    if (tid < 4) {
        int n = n0 + tid;
        dn[tid] = (n < N_NODES) ? fmaxf(d_deg[n], 1.f) : 1.f;
    }
    __syncthreads();
    int c = tid & 63, ln = tid >> 6, n = n0 + ln;
    if (n < N_NODES) {
        float s = d_agg1[n * 64 + c] / dn[ln] + b1s[c];
#pragma unroll
        for (int j = 0; j < 8; j++) s += xs[ln][j] * r1[j * 64 + c];
        d_h1[n * 64 + c] = fmaxf(s, 0.f);
    }
}

// ---------------- node update 2 + column sums for mean pool ----------------
__global__ void node_update2(const float* __restrict__ root2,
                             const float* __restrict__ bias2) {
    __shared__ float h1s[64 * 65];
    __shared__ float r2s[64 * 64];
    __shared__ float b2s[64];
    __shared__ float dn[64];
    __shared__ float colpart[4 * 64];
    int tid = threadIdx.x;
    int n0 = blockIdx.x * 64;
    for (int idx = tid; idx < 64 * 64; idx += 256) r2s[idx] = root2[idx];
    for (int idx = tid; idx < 64 * 64; idx += 256) {
        int ln = idx >> 6, kk = idx & 63;
        int n = n0 + ln;
        h1s[ln * 65 + kk] = (n < N_NODES) ? d_h1[n * 64 + kk] : 0.f;
    }
    if (tid < 64) {
        b2s[tid] = bias2[tid];
        int n = n0 + tid;
        dn[tid] = (n < N_NODES) ? fmaxf(d_deg[n], 1.f) : 1.f;
    }
    __syncthreads();
    int c = tid & 63, ng = tid >> 6;
    float csum = 0.f;
    for (int j = 0; j < 16; j++) {
        int ln = ng + 4 * j;
        int n = n0 + ln;
        if (n < N_NODES) {
            float s = d_agg2[n * 64 + c] / dn[ln] + b2s[c];
#pragma unroll 8
            for (int kk = 0; kk < 64; kk++) s += h1s[ln * 65 + kk] * r2s[kk * 64 + c];
            csum += fmaxf(s, 0.f);
        }
    }
    colpart[ng * 64 + c] = csum;
    __syncthreads();
    if (tid < 64) {
        float t = colpart[tid] + colpart[64 + tid] + colpart[128 + tid] + colpart[192 + tid];
        atomicAdd(&d_colsum[tid], t);
    }
}

// ---------------- g vector ----------------
__global__ void g_kernel(const float* __restrict__ projW, const float* __restrict__ projb) {
    __shared__ float cs[64];
    int tid = threadIdx.x;
    cs[tid] = d_colsum[tid] * (1.f / (float)N_NODES);
    __syncthreads();
    float s = projb[tid];
    for (int c = 0; c < 64; c++) s += cs[c] * projW[c * 64 + tid];
    d_g[tid] = s;
}

// ---------------- MLP layer 1 (split-K, f32x2) ----------------
__global__ void mlp1_main(const float* __restrict__ a, const float* __restrict__ mW1) {
    __shared__ __align__(16) float aT[64 * 36];
    __shared__ __align__(16) float Wt[64 * 132];
    int tid = threadIdx.x;
    int m0 = blockIdx.x * 32;
    int ks = blockIdx.y * 313;
    int ke = min(N_ACT, ks + 313);
    int tj = tid & 31, tb = tid >> 5;
    int j0 = tj * 4, b0 = tb * 4;
    ULL acc2[4][2];
#pragma unroll
    for (int p = 0; p < 4; p++) { acc2[p][0] = 0ull; acc2[p][1] = 0ull; }

    for (int kkb = ks; kkb < ke; kkb += 64) {
        int klen = ke - kkb;
        __syncthreads();
        for (int idx = tid; idx < 2048; idx += 256) {
            int b = idx >> 6, k = idx & 63;
            aT[k * 36 + b] = (k < klen) ? a[(m0 + b) * N_ACT + kkb + k] : 0.f;
        }
        for (int idx = tid; idx < 8192; idx += 256) {
            int k = idx >> 7, j = idx & 127;
            Wt[k * 132 + j] = (k < klen) ? mW1[(kkb + k) * 128 + j] : 0.f;
        }
        __syncthreads();
#pragma unroll 8
        for (int k = 0; k < 64; k++) {
            float4 av = *(const float4*)&aT[k * 36 + b0];
            const ULL* wp = (const ULL*)&Wt[k * 132 + j0];
            ULL w0 = wp[0], w1 = wp[1];
            ULL a0 = pack2(av.x), a1 = pack2(av.y);
            ULL a2 = pack2(av.z), a3 = pack2(av.w);
            fma2(acc2[0][0], a0, w0); fma2(acc2[0][1], a0, w1);
            fma2(acc2[1][0], a1, w0); fma2(acc2[1][1], a1, w1);
            fma2(acc2[2][0], a2, w0); fma2(acc2[2][1], a2, w1);
            fma2(acc2[3][0], a3, w0); fma2(acc2[3][1], a3, w1);
        }
    }
#pragma unroll
    for (int p = 0; p < 4; p++) {
        float v0, v1, v2, v3;
        unpack2(acc2[p][0], v0, v1);
        unpack2(acc2[p][1], v2, v3);
        float* yp = &d_y1[(m0 + b0 + p) * 128 + j0];
        atomicAdd(yp + 0, v0);
        atomicAdd(yp + 1, v1);
        atomicAdd(yp + 2, v2);
        atomicAdd(yp + 3, v3);
    }
}

__global__ void mlp1_finish(const float* __restrict__ mW1, const float* __restrict__ mb1) {
    __shared__ float gs[64];
    int tid = threadIdx.x;
    if (tid < 64) gs[tid] = d_g[tid];
    __syncthreads();
    int idx = blockIdx.x * 256 + tid;
    int j = idx & 127;
    float s = d_y1[idx] + mb1[j];
    for (int c = 0; c < 64; c++) s += gs[c] * mW1[(N_ACT + c) * 128 + j];
    d_z1[idx] = fmaxf(s, 0.f);
}

__global__ void mlp2_kernel(const float* __restrict__ mW2, const float* __restrict__ mb2) {
    __shared__ float zs[2][128];
    int tid = threadIdx.x;
    int b0 = blockIdx.x * 2;
    zs[tid >> 7][tid & 127] = d_z1[b0 * 128 + tid];
    __syncthreads();
    int lb = tid >> 7, j = tid & 127;
    float s = mb2[j];
#pragma unroll 4
    for (int k = 0; k < 128; k++) s += zs[lb][k] * mW2[k * 128 + j];
    d_z2[(b0 + lb) * 128 + j] = fmaxf(s, 0.f);
}

__global__ void mlp3_kernel(const float* __restrict__ mW3, const float* __restrict__ mb3,
                            float* __restrict__ out) {
    __shared__ float w3[128];
    int tid = threadIdx.x;
    if (tid < 128) w3[tid] = mW3[tid];
    __syncthreads();
    float s = mb3[0];
    for (int j = 0; j < 128; j++) s += d_z2[tid * 128 + j] * w3[j];
    out[tid] = s;
}

// ---------------- launcher ----------------
extern "C" void kernel_launch(void* const* d_in, const int* in_sizes, int n_in,
                              void* d_out, int out_size) {
    const float* x     = (const float*)d_in[0];
    const int*   ei    = (const int*)  d_in[1];
    const float* ea    = (const float*)d_in[2];
    const float* a     = (const float*)d_in[3];
    const float* e1W1  = (const float*)d_in[4];
    const float* e1b1  = (const float*)d_in[5];
    const float* e1W2  = (const float*)d_in[6];
    const float* e1b2  = (const float*)d_in[7];
    const float* root1 = (const float*)d_in[8];
    const float* bias1 = (const float*)d_in[9];
    const float* e2W1  = (const float*)d_in[10];
    const float* e2b1  = (const float*)d_in[11];
    const float* e2W2  = (const float*)d_in[12];
    const float* e2b2  = (const float*)d_in[13];
    const float* root2 = (const float*)d_in[14];
    const float* bias2 = (const float*)d_in[15];
    const float* projW = (const float*)d_in[16];
    const float* projb = (const float*)d_in[17];
    const float* mW1   = (const float*)d_in[18];
    const float* mb1   = (const float*)d_in[19];
    const float* mW2   = (const float*)d_in[20];
    const float* mb2   = (const float*)d_in[21];
    const float* mW3   = (const float*)d_in[22];
    const float* mb3   = (const float*)d_in[23];
    float* out = (float*)d_out;

    const int sg8  = 2 * 8  * 132 * 4;   //  8,448 B
    const int sg64 = 2 * 64 * 132 * 4;   // 67,584 B
    cudaFuncSetAttribute(mn_gemm<8>,  cudaFuncAttributeMaxDynamicSharedMemorySize, sg8);
    cudaFuncSetAttribute(mn_gemm<64>, cudaFuncAttributeMaxDynamicSharedMemorySize, sg64);

    dim3 ggrid((N_NODES + 127) / 128, 32);       // 157 x 32
    const int CB = (N_EDGES + 63) / 64;          // 938 consume blocks

    zero_kernel<<<512, 256>>>();
    bn_kernel<8><<<(N_NODES + 3) / 4, 256>>>(x, e1b2);
    edge_feat_kernel<<<(N_EDGES + 15) / 16, 256>>>(ea, ei, e1W1, e1b1, e2W1, e2b1);
    mn_gemm<8><<<ggrid, 256, sg8>>>(x, e1W2);
    scan_kernel<<<1, 512>>>();
    scatter_kernel<<<(N_EDGES + 255) / 256, 256>>>(ei);
    consume_kernel<1><<<CB, 256>>>(ei);
    node_update1<<<(N_NODES + 3) / 4, 256>>>(x, root1, bias1);
    bn_kernel<64><<<(N_NODES + 3) / 4, 256>>>(x, e2b2);
    mn_gemm<64><<<ggrid, 256, sg64>>>(x, e2W2);
    consume_kernel<2><<<CB, 256>>>(ei);
    node_update2<<<(N_NODES + 63) / 64, 256>>>(root2, bias2);
    g_kernel<<<1, 64>>>(projW, projb);
    mlp1_main<<<dim3(8, 64), 256>>>(a, mW1);
    mlp1_finish<<<128, 256>>>(mW1, mb1);
    mlp2_kernel<<<128, 256>>>(mW2, mb2);
    mlp3_kernel<<<1, 256>>>(mW3, mb3, out);
}

// round 11
// speedup vs baseline: 1.3150x; 1.3150x over previous
#include <cuda_runtime.h>

#define N_NODES 20000
#define N_EDGES 60000
#define NODE_IN 8
#define HID     64
#define BATCH   256
#define MLP_H   128
#define N_ACT   20000

#define NT    32     // nodes per block in nnconv
#define NTHR  256    // threads per nnconv block
#define TCAP  192    // edge-task list capacity per block
#define TMAXW 14     // register msg-accumulator slots per warp (covers 112 tasks/block)
#define WBUF  4112   // 8*514 floats per Wss buffer

typedef unsigned long long ULL;

// ---------------- device scratch ----------------
__device__ float d_h1e[N_EDGES * HID];
__device__ float d_h2e[N_EDGES * HID];
__device__ float d_deg[N_NODES];
__device__ float d_agg1[N_NODES * HID];
__device__ float d_h1[N_NODES * HID];
__device__ float d_agg2[N_NODES * HID];
__device__ float d_colsum[HID];
__device__ float d_g[HID];
__device__ float d_y1[BATCH * MLP_H];
__device__ float d_z1[BATCH * MLP_H];
__device__ float d_z2[BATCH * MLP_H];
__device__ float d_bn1[N_NODES * HID];
__device__ float d_bn2[N_NODES * HID];
// CSR by src
__device__ int d_srccnt[N_NODES];
__device__ int d_fill[N_NODES];
__device__ int d_srcptr[N_NODES + 1];
__device__ int d_elist[N_EDGES];

// f32x2 packed helpers
__device__ __forceinline__ ULL pack2(float v) {
    ULL r;
    asm("mov.b64 %0, {%1, %1};" : "=l"(r) : "f"(v));
    return r;
}
__device__ __forceinline__ void fma2(ULL& acc, ULL a, ULL b) {
    asm("fma.rn.f32x2 %0, %1, %2, %0;" : "+l"(acc) : "l"(a), "l"(b));
}
__device__ __forceinline__ void unpack2(ULL v, float& lo, float& hi) {
    asm("mov.b64 {%0, %1}, %2;" : "=f"(lo), "=f"(hi) : "l"(v));
}
// cp.async helpers
__device__ __forceinline__ void cpa8(unsigned dst, const void* src) {
    asm volatile("cp.async.ca.shared.global [%0], [%1], 8;" :: "r"(dst), "l"(src) : "memory");
}
__device__ __forceinline__ void cpa_commit() {
    asm volatile("cp.async.commit_group;" ::: "memory");
}
template<int N> __device__ __forceinline__ void cpa_wait() {
    asm volatile("cp.async.wait_group %0;" :: "n"(N) : "memory");
}

// ---------------- zero scratch ----------------
__global__ void zero_kernel() {
    int i  = blockIdx.x * blockDim.x + threadIdx.x;
    int gs = gridDim.x * blockDim.x;
    for (int j = i; j < N_NODES * HID; j += gs) { d_agg1[j] = 0.f; d_agg2[j] = 0.f; }
    for (int j = i; j < N_NODES; j += gs) { d_deg[j] = 0.f; d_srccnt[j] = 0; d_fill[j] = 0; }
    for (int j = i; j < BATCH * MLP_H; j += gs) d_y1[j] = 0.f;
    if (i < HID) d_colsum[i] = 0.f;
}

// ---------------- edge feature MLPs + degree counts ----------------
__global__ void edge_feat_kernel(const float* __restrict__ edge_attr,
                                 const int*   __restrict__ edge_index,
                                 const float* __restrict__ W1a, const float* __restrict__ b1a,
                                 const float* __restrict__ W1b, const float* __restrict__ b1b) {
    __shared__ float wa[256], wb[256], ba[64], bb[64], ea[16][4];
    int tid = threadIdx.x;
    wa[tid] = W1a[tid];
    wb[tid] = W1b[tid];
    if (tid < 64) { ba[tid] = b1a[tid]; bb[tid] = b1b[tid]; }
    int e0 = blockIdx.x * 16;
    if (tid < 64) {
        int le = tid >> 2, j = tid & 3;
        int e = e0 + le;
        ea[le][j] = (e < N_EDGES) ? edge_attr[e * 4 + j] : 0.f;
    }
    __syncthreads();
    int c = tid & 63;
#pragma unroll
    for (int ch = 0; ch < 4; ch++) {
        int le = (tid >> 6) + ch * 4;
        int e = e0 + le;
        if (e < N_EDGES) {
            float s1 = ba[c], s2 = bb[c];
#pragma unroll
            for (int j = 0; j < 4; j++) {
                s1 += ea[le][j] * wa[j * 64 + c];
                s2 += ea[le][j] * wb[j * 64 + c];
            }
            d_h1e[e * 64 + c] = fmaxf(s1, 0.f);
            d_h2e[e * 64 + c] = fmaxf(s2, 0.f);
            if (c == 0) atomicAdd(&d_deg[edge_index[N_EDGES + e]], 1.f);
            if (c == 1) atomicAdd(&d_srccnt[edge_index[e]], 1);
        }
    }
}

// ---------------- fused exclusive scan + CSR scatter (single block) ----------------
__global__ void scanscatter_kernel(const int* __restrict__ edge_index) {
    __shared__ int part[1024];
    int tid = threadIdx.x;
    const int CH = (N_NODES + 1023) / 1024;   // 20
    int base = tid * CH;
    int s = 0;
    for (int j = 0; j < CH; j++) {
        int idx = base + j;
        if (idx < N_NODES) s += d_srccnt[idx];
    }
    part[tid] = s;
    __syncthreads();
    for (int off = 1; off < 1024; off <<= 1) {
        int v = (tid >= off) ? part[tid - off] : 0;
        __syncthreads();
        part[tid] += v;
        __syncthreads();
    }
    int run = (tid > 0) ? part[tid - 1] : 0;
    for (int j = 0; j < CH; j++) {
        int idx = base + j;
        if (idx < N_NODES) { d_srcptr[idx] = run; run += d_srccnt[idx]; }
    }
    if (tid == 1023) d_srcptr[N_NODES] = run;
    __syncthreads();
    // scatter edges into CSR lists
    for (int e = tid; e < N_EDGES; e += 1024) {
        int sv = edge_index[e];
        int pos = d_srcptr[sv] + atomicAdd(&d_fill[sv], 1);
        d_elist[pos] = e;
    }
}

// ---------------- W2 tile prefetch (cp.async, 8B) ----------------
template<int IDIM>
__device__ __forceinline__ void stage_w2(const float* __restrict__ W2,
                                         unsigned wss_smem, int kc, int is, int tid) {
    constexpr int WROW = IDIM * 64;
#pragma unroll
    for (int j = 0; j < 8; j++) {
        int p2 = tid + j * NTHR;          // pair index 0..2047
        int o2 = p2 & 31;
        int ks = (p2 >> 5) & 7;
        int ii = p2 >> 8;
        const float* src = W2 + (kc * 8 + ks) * WROW + (is * 8 + ii) * 64 + o2 * 2;
        unsigned dst = wss_smem + (unsigned)((ks * 514 + ii * 64 + o2 * 2) * 4);
        cpa8(dst, src);
    }
}

// ---------------- NNConv: per-NODE weight GEMM (f32x2), k-chunked,
//                  double-buffered W2 staging, register msg accumulators ----
template<int IDIM>
__launch_bounds__(NTHR, 2)
__global__ void nnconv_kernel(const float* __restrict__ xin_param,
                              const float* __restrict__ W2,
                              const float* __restrict__ b2,
                              const int*   __restrict__ edge_index) {
    const float* xin = (IDIM == 8) ? xin_param : d_h1;
    const float* hE  = (IDIM == 8) ? d_h1e : d_h2e;
    float*       agg = (IDIM == 8) ? d_agg1 : d_agg2;
    float*       bno = (IDIM == 8) ? d_bn1 : d_bn2;
    const int*   srcp = edge_index;
    const int*   dstp = edge_index + N_EDGES;

    constexpr int IS   = IDIM / 8;   // i-stages per k-chunk
    constexpr int NST  = 8 * IS;     // total stages
    constexpr int XR   = 36;         // xsT row stride
    constexpr int MKS  = 66;         // Mns per-k stride
    constexpr int MNS  = 8 * MKS;    // 528 per node

    extern __shared__ float sm[];
    float* xsT  = sm;                         // [IDIM][XR]   xsT[i][n]
    float* Wss  = xsT + IDIM * XR;            // [2][8][514]  double-buffered W2 tile
    float* Mns  = Wss + 2 * WBUF;             // [NT][8k][66] (head reused for b2)
    int*  tasks = (int*)(Mns + NT * MNS);     // [TCAP]  (ln<<24)|e
    int*  taskD = tasks + TCAP;               // [TCAP]  dst
    int*  sNT   = taskD + TCAP;               // [2]: ntask, csr0

    int tid = threadIdx.x;
    int nb0 = blockIdx.x * NT;
    unsigned wss_base = (unsigned)__cvta_generic_to_shared(Wss);

    // kick off pipeline: stage 0 into buffer 0 (overlaps prologue)
    stage_w2<IDIM>(W2, wss_base, 0, 0, tid);
    cpa_commit();

    // transposed node features
    for (int idx = tid; idx < NT * IDIM; idx += NTHR) {
        int i = idx % IDIM, n = idx / IDIM;
        int gn = nb0 + n;
        xsT[i * XR + n] = (gn < N_NODES) ? xin[gn * IDIM + i] : 0.f;
    }
    if (tid == 0) {
        int c0 = d_srcptr[nb0];
        int hi = nb0 + NT; if (hi > N_NODES) hi = N_NODES;
        sNT[0] = d_srcptr[hi] - c0;
        sNT[1] = c0;
    }
    // stage b2 (flat) into Mns head (free until first Mn store)
    for (int idx = tid; idx < IDIM * 64; idx += NTHR) Mns[idx] = b2[idx];
    __syncthreads();
    int ntask = sNT[0];
    int csr0  = sNT[1];
    // task lists
    for (int t = tid; t < ntask && t < TCAP; t += NTHR) {
        int e = d_elist[csr0 + t];
        tasks[t] = ((srcp[e] - nb0) << 24) | e;
        taskD[t] = dstp[e];
    }
    // bn[n][o] = sum_i xsT[i][n] * b2[i*64+o]  -> global scratch (freed smem)
    for (int idx = tid; idx < NT * 64; idx += NTHR) {
        int o = idx & 63, n = idx >> 6;
        float s = 0.f;
#pragma unroll 8
        for (int i = 0; i < IDIM; i++) s += xsT[i * XR + n] * Mns[i * 64 + o];
        int gn = nb0 + n;
        if (gn < N_NODES) bno[gn * 64 + o] = s;
    }

    int q  = tid >> 6;       // node oct (warp-uniform): nodes q*8..q*8+7
    int rr = tid & 63;
    int kk = rr >> 3;        // k within chunk
    int oh = rr & 7;         // o octet
    int w = tid >> 5, l = tid & 31;
    int o2 = 2 * l;
    int lim = (ntask < 8 * TMAXW) ? ntask : 8 * TMAXW;

    // per-warp register message accumulators (outputs o2, o2+1 packed)
    ULL accM[TMAXW];
#pragma unroll
    for (int i = 0; i < TMAXW; i++) accM[i] = 0ull;

    int buf = 0;
    for (int kc = 0; kc < 8; kc++) {
        ULL acc[8][4];
#pragma unroll
        for (int a = 0; a < 8; a++)
#pragma unroll
            for (int p = 0; p < 4; p++) acc[a][p] = 0ull;

        for (int is = 0; is < IS; is++) {
            __syncthreads();   // buf^1 readers done (2 stages ago) / prev-kc Mns readers done
            int sn = kc * IS + is + 1;
            if (sn < NST) {
                stage_w2<IDIM>(W2, wss_base + (unsigned)((buf ^ 1) * WBUF * 4),
                               sn / IS, sn % IS, tid);
                cpa_commit();
                cpa_wait<1>();   // current stage's copy complete; next may fly
            } else {
                cpa_wait<0>();
            }
            __syncthreads();     // current buffer visible to all

            const float* Wc = Wss + buf * WBUF;
#pragma unroll
            for (int ii = 0; ii < 8; ii++) {
                int i = is * 8 + ii;
                const float4* xr = (const float4*)(xsT + i * XR + q * 8);
                float4 xa = xr[0], xb = xr[1];
                ULL h[8];
                h[0] = pack2(xa.x); h[1] = pack2(xa.y); h[2] = pack2(xa.z); h[3] = pack2(xa.w);
                h[4] = pack2(xb.x); h[5] = pack2(xb.y); h[6] = pack2(xb.z); h[7] = pack2(xb.w);
                const ULL* wp = (const ULL*)(Wc + kk * 514 + ii * 64 + oh * 8);
#pragma unroll
                for (int p = 0; p < 4; p++) {
                    ULL wv = wp[p];
                    fma2(acc[0][p], h[0], wv); fma2(acc[1][p], h[1], wv);
                    fma2(acc[2][p], h[2], wv); fma2(acc[3][p], h[3], wv);
                    fma2(acc[4][p], h[4], wv); fma2(acc[5][p], h[5], wv);
                    fma2(acc[6][p], h[6], wv); fma2(acc[7][p], h[7], wv);
                }
            }
            buf ^= 1;
        }

        // store Mn chunk (conflict-free: bank-pair = kk + 4*oh per warp)
#pragma unroll
        for (int a = 0; a < 8; a++) {
            ULL* mp = (ULL*)(Mns + (q * 8 + a) * MNS + kk * MKS + oh * 8);
#pragma unroll
            for (int p = 0; p < 4; p++) mp[p] = acc[a][p];
        }
        __syncthreads();

        // ---- consume owned tasks into registers (no atomics) ----
        {
            int hb = kc * 8 + (l & 7);
            int pk_n = 0; float hv_n = 0.f;
            if (w < lim) {
                pk_n = tasks[w];
                hv_n = hE[(pk_n & 0xFFFFFF) * 64 + hb];
            }
#pragma unroll
            for (int i = 0; i < TMAXW; i++) {
                int t = w + i * 8;
                if (t >= lim) break;
                int pk = pk_n; float hv = hv_n;
                int tn = t + 8;
                if (tn < lim) {
                    pk_n = tasks[tn];
                    hv_n = hE[(pk_n & 0xFFFFFF) * 64 + hb];
                }
                int ln = pk >> 24;
                const float* mp = Mns + ln * MNS + o2;
#pragma unroll
                for (int k = 0; k < 8; k++) {
                    float hk = __shfl_sync(0xFFFFFFFFu, hv, k);
                    fma2(accM[i], pack2(hk), *(const ULL*)(mp + k * MKS));
                }
            }
        }
        // ---- overflow tasks (rare): per-chunk atomic path ----
        for (int t = 8 * TMAXW + w; t < ntask; t += 8) {
            int e, ln, d;
            if (t < TCAP) { int pk = tasks[t]; ln = pk >> 24; e = pk & 0xFFFFFF; d = taskD[t]; }
            else { e = d_elist[csr0 + t]; ln = srcp[e] - nb0; d = dstp[e]; }
            float hv = hE[e * 64 + kc * 8 + (l & 7)];
            ULL s2 = 0ull;
            const float* mp = Mns + ln * MNS + o2;
#pragma unroll
            for (int k = 0; k < 8; k++) {
                float hk = __shfl_sync(0xFFFFFFFFu, hv, k);
                fma2(s2, pack2(hk), *(const ULL*)(mp + k * MKS));
            }
            float a0, a1; unpack2(s2, a0, a1);
            if (kc == 0) {
                a0 += __ldg(&bno[(nb0 + ln) * 64 + o2]);
                a1 += __ldg(&bno[(nb0 + ln) * 64 + o2 + 1]);
            }
            atomicAdd(&agg[d * 64 + o2], a0);
            atomicAdd(&agg[d * 64 + o2 + 1], a1);
        }
    }

    // ---- single commit of register-accumulated messages ----
#pragma unroll
    for (int i = 0; i < TMAXW; i++) {
        int t = w + i * 8;
        if (t >= lim) break;
        int pk = tasks[t];
        int ln = pk >> 24;
        int d  = taskD[t];
        float a0, a1; unpack2(accM[i], a0, a1);
        a0 += __ldg(&bno[(nb0 + ln) * 64 + o2]);
        a1 += __ldg(&bno[(nb0 + ln) * 64 + o2 + 1]);
        atomicAdd(&agg[d * 64 + o2], a0);
        atomicAdd(&agg[d * 64 + o2 + 1], a1);
    }
}

// ---------------- node update 1 ----------------
__global__ void node_update1(const float* __restrict__ x,
                             const float* __restrict__ root1,
                             const float* __restrict__ bias1) {
    __shared__ float r1[512], b1s[64], xs[4][8], dn[4];
    int tid = threadIdx.x;
    r1[tid] = root1[tid];
    r1[tid + 256] = root1[tid + 256];
    if (tid < 64) b1s[tid] = bias1[tid];
    int n0 = blockIdx.x * 4;
    if (tid < 32) {
        int ln = tid >> 3, j = tid & 7;
        int n = n0 + ln;
        xs[ln][j] = (n < N_NODES) ? x[n * 8 + j] : 0.f;
    }
    if (tid < 4) {
        int n = n0 + tid;
        dn[tid] = (n < N_NODES) ? fmaxf(d_deg[n], 1.f) : 1.f;
    }
    __syncthreads();
    int c = tid & 63, ln = tid >> 6, n = n0 + ln;
    if (n < N_NODES) {
        float s = d_agg1[n * 64 + c] / dn[ln] + b1s[c];
#pragma unroll
        for (int j = 0; j < 8; j++) s += xs[ln][j] * r1[j * 64 + c];
        d_h1[n * 64 + c] = fmaxf(s, 0.f);
    }
}

// ---------------- node update 2 + column sums for mean pool ----------------
__global__ void node_update2(const float* __restrict__ root2,
                             const float* __restrict__ bias2) {
    __shared__ float h1s[64 * 65];
    __shared__ float r2s[64 * 64];
    __shared__ float b2s[64];
    __shared__ float dn[64];
    __shared__ float colpart[4 * 64];
    int tid = threadIdx.x;
    int n0 = blockIdx.x * 64;
    for (int idx = tid; idx < 64 * 64; idx += 256) r2s[idx] = root2[idx];
    for (int idx = tid; idx < 64 * 64; idx += 256) {
        int ln = idx >> 6, kk = idx & 63;
        int n = n0 + ln;
        h1s[ln * 65 + kk] = (n < N_NODES) ? d_h1[n * 64 + kk] : 0.f;
    }
    if (tid < 64) {
        b2s[tid] = bias2[tid];
        int n = n0 + tid;
        dn[tid] = (n < N_NODES) ? fmaxf(d_deg[n], 1.f) : 1.f;
    }
    __syncthreads();
    int c = tid & 63, ng = tid >> 6;
    float csum = 0.f;
    for (int j = 0; j < 16; j++) {
        int ln = ng + 4 * j;
        int n = n0 + ln;
        if (n < N_NODES) {
            float s = d_agg2[n * 64 + c] / dn[ln] + b2s[c];
#pragma unroll 8
            for (int kk = 0; kk < 64; kk++) s += h1s[ln * 65 + kk] * r2s[kk * 64 + c];
            csum += fmaxf(s, 0.f);
        }
    }
    colpart[ng * 64 + c] = csum;
    __syncthreads();
    if (tid < 64) {
        float t = colpart[tid] + colpart[64 + tid] + colpart[128 + tid] + colpart[192 + tid];
        atomicAdd(&d_colsum[tid], t);
    }
}

// ---------------- g vector ----------------
__global__ void g_kernel(const float* __restrict__ projW, const float* __restrict__ projb) {
    __shared__ float cs[64];
    int tid = threadIdx.x;
    cs[tid] = d_colsum[tid] * (1.f / (float)N_NODES);
    __syncthreads();
    float s = projb[tid];
    for (int c = 0; c < 64; c++) s += cs[c] * projW[c * 64 + tid];
    d_g[tid] = s;
}

// ---------------- MLP layer 1 (split-K, f32x2) ----------------
__global__ void mlp1_main(const float* __restrict__ a, const float* __restrict__ mW1) {
    __shared__ __align__(16) float aT[64 * 36];
    __shared__ __align__(16) float Wt[64 * 132];
    int tid = threadIdx.x;
    int m0 = blockIdx.x * 32;
    int ks = blockIdx.y * 313;
    int ke = min(N_ACT, ks + 313);
    int tj = tid & 31, tb = tid >> 5;
    int j0 = tj * 4, b0 = tb * 4;
    ULL acc2[4][2];
#pragma unroll
    for (int p = 0; p < 4; p++) { acc2[p][0] = 0ull; acc2[p][1] = 0ull; }

    for (int kkb = ks; kkb < ke; kkb += 64) {
        int klen = ke - kkb;
        __syncthreads();
        for (int idx = tid; idx < 2048; idx += 256) {
            int b = idx >> 6, k = idx & 63;
            aT[k * 36 + b] = (k < klen) ? a[(m0 + b) * N_ACT + kkb + k] : 0.f;
        }
        for (int idx = tid; idx < 8192; idx += 256) {
            int k = idx >> 7, j = idx & 127;
            Wt[k * 132 + j] = (k < klen) ? mW1[(kkb + k) * 128 + j] : 0.f;
        }
        __syncthreads();
#pragma unroll 8
        for (int k = 0; k < 64; k++) {
            float4 av = *(const float4*)&aT[k * 36 + b0];
            const ULL* wp = (const ULL*)&Wt[k * 132 + j0];
            ULL w0 = wp[0], w1 = wp[1];
            ULL a0 = pack2(av.x), a1 = pack2(av.y);
            ULL a2 = pack2(av.z), a3 = pack2(av.w);
            fma2(acc2[0][0], a0, w0); fma2(acc2[0][1], a0, w1);
            fma2(acc2[1][0], a1, w0); fma2(acc2[1][1], a1, w1);
            fma2(acc2[2][0], a2, w0); fma2(acc2[2][1], a2, w1);
            fma2(acc2[3][0], a3, w0); fma2(acc2[3][1], a3, w1);
        }
    }
#pragma unroll
    for (int p = 0; p < 4; p++) {
        float v0, v1, v2, v3;
        unpack2(acc2[p][0], v0, v1);
        unpack2(acc2[p][1], v2, v3);
        float* yp = &d_y1[(m0 + b0 + p) * 128 + j0];
        atomicAdd(yp + 0, v0);
        atomicAdd(yp + 1, v1);
        atomicAdd(yp + 2, v2);
        atomicAdd(yp + 3, v3);
    }
}

__global__ void mlp1_finish(const float* __restrict__ mW1, const float* __restrict__ mb1) {
    __shared__ float gs[64];
    int tid = threadIdx.x;
    if (tid < 64) gs[tid] = d_g[tid];
    __syncthreads();
    int idx = blockIdx.x * 256 + tid;
    int j = idx & 127;
    float s = d_y1[idx] + mb1[j];
    for (int c = 0; c < 64; c++) s += gs[c] * mW1[(N_ACT + c) * 128 + j];
    d_z1[idx] = fmaxf(s, 0.f);
}

__global__ void mlp2_kernel(const float* __restrict__ mW2, const float* __restrict__ mb2) {
    __shared__ float zs[2][128];
    int tid = threadIdx.x;
    int b0 = blockIdx.x * 2;
    zs[tid >> 7][tid & 127] = d_z1[b0 * 128 + tid];
    __syncthreads();
    int lb = tid >> 7, j = tid & 127;
    float s = mb2[j];
#pragma unroll 4
    for (int k = 0; k < 128; k++) s += zs[lb][k] * mW2[k * 128 + j];
    d_z2[(b0 + lb) * 128 + j] = fmaxf(s, 0.f);
}

__global__ void mlp3_kernel(const float* __restrict__ mW3, const float* __restrict__ mb3,
                            float* __restrict__ out) {
    __shared__ float w3[128];
    int tid = threadIdx.x;
    if (tid < 128) w3[tid] = mW3[tid];
    __syncthreads();
    float s = mb3[0];
    for (int j = 0; j < 128; j++) s += d_z2[tid * 128 + j] * w3[j];
    out[tid] = s;
}

// ---------------- launcher ----------------
extern "C" void kernel_launch(void* const* d_in, const int* in_sizes, int n_in,
                              void* d_out, int out_size) {
    const float* x     = (const float*)d_in[0];
    const int*   ei    = (const int*)  d_in[1];
    const float* ea    = (const float*)d_in[2];
    const float* a     = (const float*)d_in[3];
    const float* e1W1  = (const float*)d_in[4];
    const float* e1b1  = (const float*)d_in[5];
    const float* e1W2  = (const float*)d_in[6];
    const float* e1b2  = (const float*)d_in[7];
    const float* root1 = (const float*)d_in[8];
    const float* bias1 = (const float*)d_in[9];
    const float* e2W1  = (const float*)d_in[10];
    const float* e2b1  = (const float*)d_in[11];
    const float* e2W2  = (const float*)d_in[12];
    const float* e2b2  = (const float*)d_in[13];
    const float* root2 = (const float*)d_in[14];
    const float* bias2 = (const float*)d_in[15];
    const float* projW = (const float*)d_in[16];
    const float* projb = (const float*)d_in[17];
    const float* mW1   = (const float*)d_in[18];
    const float* mb1   = (const float*)d_in[19];
    const float* mW2   = (const float*)d_in[20];
    const float* mb2   = (const float*)d_in[21];
    const float* mW3   = (const float*)d_in[22];
    const float* mb3   = (const float*)d_in[23];
    float* out = (float*)d_out;

    // smem (floats): xsT + Wss(2*4112) + Mns(32*528) + tasks + taskD + 2
    const int sbase = (2 * WBUF + NT * 528 + TCAP + TCAP + 2);
    const int s8  = (8  * 36 + sbase) * 4;   // ~103.2 KB
    const int s64 = (64 * 36 + sbase) * 4;   // ~111.2 KB -> 2 blocks/SM
    cudaFuncSetAttribute(nnconv_kernel<8>,  cudaFuncAttributeMaxDynamicSharedMemorySize, s8);
    cudaFuncSetAttribute(nnconv_kernel<64>, cudaFuncAttributeMaxDynamicSharedMemorySize, s64);

    const int NB = (N_NODES + NT - 1) / NT;   // 625

    zero_kernel<<<512, 256>>>();                                           // 0
    edge_feat_kernel<<<(N_EDGES + 15) / 16, 256>>>(ea, ei, e1W1, e1b1,
                                                   e2W1, e2b1);            // 1
    scanscatter_kernel<<<1, 1024>>>(ei);                                   // 2
    nnconv_kernel<8><<<NB, NTHR, s8>>>(x, e1W2, e1b2, ei);                 // 3 (profiled)
    node_update1<<<(N_NODES + 3) / 4, 256>>>(x, root1, bias1);             // 4
    nnconv_kernel<64><<<NB, NTHR, s64>>>(x, e2W2, e2b2, ei);               // 5
    node_update2<<<(N_NODES + 63) / 64, 256>>>(root2, bias2);              // 6
    g_kernel<<<1, 64>>>(projW, projb);                                     // 7
    mlp1_main<<<dim3(8, 64), 256>>>(a, mW1);                               // 8
    mlp1_finish<<<128, 256>>>(mW1, mb1);                                   // 9
    mlp2_kernel<<<128, 256>>>(mW2, mb2);                                   // 10
    mlp3_kernel<<<1, 256>>>(mW3, mb3, out);                                // 11
}

// round 12
// speedup vs baseline: 1.3388x; 1.0181x over previous
#include <cuda_runtime.h>

#define N_NODES 20000
#define N_EDGES 60000
#define NODE_IN 8
#define HID     64
#define BATCH   256
#define MLP_H   128
#define N_ACT   20000

#define NT    32     // nodes per block in nnconv
#define NTHR  256    // threads per nnconv block
#define TCAP  192    // edge-task list capacity per block
#define WBUF  4112   // 8*514 floats per Wss buffer

typedef unsigned long long ULL;

// ---------------- device scratch ----------------
__device__ float d_h1e[N_EDGES * HID];
__device__ float d_h2e[N_EDGES * HID];
__device__ float d_deg[N_NODES];
__device__ float d_agg1[N_NODES * HID];
__device__ float d_h1[N_NODES * HID];
__device__ float d_agg2[N_NODES * HID];
__device__ float d_colsum[HID];
__device__ float d_g[HID];
__device__ float d_y1[BATCH * MLP_H];
__device__ float d_z1[BATCH * MLP_H];
__device__ float d_z2[BATCH * MLP_H];
__device__ float d_bn1[N_NODES * HID];
__device__ float d_bn2[N_NODES * HID];
// CSR by src
__device__ int d_srccnt[N_NODES];
__device__ int d_fill[N_NODES];
__device__ int d_srcptr[N_NODES + 1];
__device__ int d_elist[N_EDGES];

// f32x2 packed helpers
__device__ __forceinline__ ULL pack2(float v) {
    ULL r;
    asm("mov.b64 %0, {%1, %1};" : "=l"(r) : "f"(v));
    return r;
}
__device__ __forceinline__ void fma2(ULL& acc, ULL a, ULL b) {
    asm("fma.rn.f32x2 %0, %1, %2, %0;" : "+l"(acc) : "l"(a), "l"(b));
}
__device__ __forceinline__ void unpack2(ULL v, float& lo, float& hi) {
    asm("mov.b64 {%0, %1}, %2;" : "=f"(lo), "=f"(hi) : "l"(v));
}
// cp.async helpers
__device__ __forceinline__ void cpa8(unsigned dst, const void* src) {
    asm volatile("cp.async.ca.shared.global [%0], [%1], 8;" :: "r"(dst), "l"(src) : "memory");
}
__device__ __forceinline__ void cpa_commit() {
    asm volatile("cp.async.commit_group;" ::: "memory");
}
template<int N> __device__ __forceinline__ void cpa_wait() {
    asm volatile("cp.async.wait_group %0;" :: "n"(N) : "memory");
}

// ---------------- zero scratch ----------------
__global__ void zero_kernel() {
    int i  = blockIdx.x * blockDim.x + threadIdx.x;
    int gs = gridDim.x * blockDim.x;
    for (int j = i; j < N_NODES * HID; j += gs) { d_agg1[j] = 0.f; d_agg2[j] = 0.f; }
    for (int j = i; j < N_NODES; j += gs) { d_deg[j] = 0.f; d_srccnt[j] = 0; d_fill[j] = 0; }
    for (int j = i; j < BATCH * MLP_H; j += gs) d_y1[j] = 0.f;
    if (i < HID) d_colsum[i] = 0.f;
}

// ---------------- edge feature MLPs + degree counts ----------------
__global__ void edge_feat_kernel(const float* __restrict__ edge_attr,
                                 const int*   __restrict__ edge_index,
                                 const float* __restrict__ W1a, const float* __restrict__ b1a,
                                 const float* __restrict__ W1b, const float* __restrict__ b1b) {
    __shared__ float wa[256], wb[256], ba[64], bb[64], ea[16][4];
    int tid = threadIdx.x;
    wa[tid] = W1a[tid];
    wb[tid] = W1b[tid];
    if (tid < 64) { ba[tid] = b1a[tid]; bb[tid] = b1b[tid]; }
    int e0 = blockIdx.x * 16;
    if (tid < 64) {
        int le = tid >> 2, j = tid & 3;
        int e = e0 + le;
        ea[le][j] = (e < N_EDGES) ? edge_attr[e * 4 + j] : 0.f;
    }
    __syncthreads();
    int c = tid & 63;
#pragma unroll
    for (int ch = 0; ch < 4; ch++) {
        int le = (tid >> 6) + ch * 4;
        int e = e0 + le;
        if (e < N_EDGES) {
            float s1 = ba[c], s2 = bb[c];
#pragma unroll
            for (int j = 0; j < 4; j++) {
                s1 += ea[le][j] * wa[j * 64 + c];
                s2 += ea[le][j] * wb[j * 64 + c];
            }
            d_h1e[e * 64 + c] = fmaxf(s1, 0.f);
            d_h2e[e * 64 + c] = fmaxf(s2, 0.f);
            if (c == 0) atomicAdd(&d_deg[edge_index[N_EDGES + e]], 1.f);
            if (c == 1) atomicAdd(&d_srccnt[edge_index[e]], 1);
        }
    }
}

// ---------------- fused exclusive scan + CSR scatter (single block) ----------------
__global__ void scanscatter_kernel(const int* __restrict__ edge_index) {
    __shared__ int part[1024];
    int tid = threadIdx.x;
    const int CH = (N_NODES + 1023) / 1024;   // 20
    int base = tid * CH;
    int s = 0;
    for (int j = 0; j < CH; j++) {
        int idx = base + j;
        if (idx < N_NODES) s += d_srccnt[idx];
    }
    part[tid] = s;
    __syncthreads();
    for (int off = 1; off < 1024; off <<= 1) {
        int v = (tid >= off) ? part[tid - off] : 0;
        __syncthreads();
        part[tid] += v;
        __syncthreads();
    }
    int run = (tid > 0) ? part[tid - 1] : 0;
    for (int j = 0; j < CH; j++) {
        int idx = base + j;
        if (idx < N_NODES) { d_srcptr[idx] = run; run += d_srccnt[idx]; }
    }
    if (tid == 1023) d_srcptr[N_NODES] = run;
    __syncthreads();
    // scatter edges into CSR lists
    for (int e = tid; e < N_EDGES; e += 1024) {
        int sv = edge_index[e];
        int pos = d_srcptr[sv] + atomicAdd(&d_fill[sv], 1);
        d_elist[pos] = e;
    }
}

// ---------------- W2 tile prefetch (cp.async, 8B) ----------------
template<int IDIM>
__device__ __forceinline__ void stage_w2(const float* __restrict__ W2,
                                         unsigned wss_smem, int kc, int is, int tid) {
    constexpr int WROW = IDIM * 64;
#pragma unroll
    for (int j = 0; j < 8; j++) {
        int p2 = tid + j * NTHR;          // pair index 0..2047
        int o2 = p2 & 31;
        int ks = (p2 >> 5) & 7;
        int ii = p2 >> 8;
        const float* src = W2 + (kc * 8 + ks) * WROW + (is * 8 + ii) * 64 + o2 * 2;
        unsigned dst = wss_smem + (unsigned)((ks * 514 + ii * 64 + o2 * 2) * 4);
        cpa8(dst, src);
    }
}

// ---------------- NNConv: per-NODE weight GEMM (f32x2), k-chunked,
//                  double-buffered W2 staging, per-chunk atomic commit ----
template<int IDIM>
__launch_bounds__(NTHR, 2)
__global__ void nnconv_kernel(const float* __restrict__ xin_param,
                              const float* __restrict__ W2,
                              const float* __restrict__ b2,
                              const int*   __restrict__ edge_index) {
    const float* xin = (IDIM == 8) ? xin_param : d_h1;
    const float* hE  = (IDIM == 8) ? d_h1e : d_h2e;
    float*       agg = (IDIM == 8) ? d_agg1 : d_agg2;
    float*       bno = (IDIM == 8) ? d_bn1 : d_bn2;
    const int*   srcp = edge_index;
    const int*   dstp = edge_index + N_EDGES;

    constexpr int IS   = IDIM / 8;   // i-stages per k-chunk
    constexpr int NST  = 8 * IS;     // total stages
    constexpr int XR   = 36;         // xsT row stride
    constexpr int MKS  = 66;         // Mns per-k stride
    constexpr int MNS  = 8 * MKS;    // 528 per node

    extern __shared__ float sm[];
    float* xsT  = sm;                         // [IDIM][XR]   xsT[i][n]
    float* Wss  = xsT + IDIM * XR;            // [2][8][514]  double-buffered W2 tile
    float* Mns  = Wss + 2 * WBUF;             // [NT][8k][66] (head reused for b2)
    int*  tasks = (int*)(Mns + NT * MNS);     // [TCAP]  (ln<<24)|e
    int*  taskD = tasks + TCAP;               // [TCAP]  dst
    int*  sNT   = taskD + TCAP;               // [2]: ntask, csr0

    int tid = threadIdx.x;
    int nb0 = blockIdx.x * NT;
    unsigned wss_base = (unsigned)__cvta_generic_to_shared(Wss);

    // kick off pipeline: stage 0 into buffer 0 (overlaps prologue)
    stage_w2<IDIM>(W2, wss_base, 0, 0, tid);
    cpa_commit();

    // transposed node features
    for (int idx = tid; idx < NT * IDIM; idx += NTHR) {
        int i = idx % IDIM, n = idx / IDIM;
        int gn = nb0 + n;
        xsT[i * XR + n] = (gn < N_NODES) ? xin[gn * IDIM + i] : 0.f;
    }
    if (tid == 0) {
        int c0 = d_srcptr[nb0];
        int hi = nb0 + NT; if (hi > N_NODES) hi = N_NODES;
        sNT[0] = d_srcptr[hi] - c0;
        sNT[1] = c0;
    }
    // stage b2 (flat) into Mns head (free until first Mn store)
    for (int idx = tid; idx < IDIM * 64; idx += NTHR) Mns[idx] = b2[idx];
    __syncthreads();
    int ntask = sNT[0];
    int csr0  = sNT[1];
    // task lists
    for (int t = tid; t < ntask && t < TCAP; t += NTHR) {
        int e = d_elist[csr0 + t];
        tasks[t] = ((srcp[e] - nb0) << 24) | e;
        taskD[t] = dstp[e];
    }
    // bn[n][o] = sum_i xsT[i][n] * b2[i*64+o]  -> global scratch (freed smem)
    for (int idx = tid; idx < NT * 64; idx += NTHR) {
        int o = idx & 63, n = idx >> 6;
        float s = 0.f;
#pragma unroll 8
        for (int i = 0; i < IDIM; i++) s += xsT[i * XR + n] * Mns[i * 64 + o];
        int gn = nb0 + n;
        if (gn < N_NODES) bno[gn * 64 + o] = s;
    }

    int q  = tid >> 6;       // node oct (warp-uniform): nodes q*8..q*8+7
    int rr = tid & 63;
    int kk = rr >> 3;        // k within chunk
    int oh = rr & 7;         // o octet
    int w = tid >> 5, l = tid & 31;
    int o2 = 2 * l;

    int buf = 0;
    for (int kc = 0; kc < 8; kc++) {
        ULL acc[8][4];
#pragma unroll
        for (int a = 0; a < 8; a++)
#pragma unroll
            for (int p = 0; p < 4; p++) acc[a][p] = 0ull;

        for (int is = 0; is < IS; is++) {
            __syncthreads();   // buf^1 readers done / prev-kc Mns readers done
            int sn = kc * IS + is + 1;
            if (sn < NST) {
                stage_w2<IDIM>(W2, wss_base + (unsigned)((buf ^ 1) * WBUF * 4),
                               sn / IS, sn % IS, tid);
                cpa_commit();
                cpa_wait<1>();   // current stage's copy complete; next may fly
            } else {
                cpa_wait<0>();
            }
            __syncthreads();     // current buffer visible to all

            const float* Wc = Wss + buf * WBUF;
#pragma unroll
            for (int ii = 0; ii < 8; ii++) {
                int i = is * 8 + ii;
                const float4* xr = (const float4*)(xsT + i * XR + q * 8);
                float4 xa = xr[0], xb = xr[1];
                ULL h[8];
                h[0] = pack2(xa.x); h[1] = pack2(xa.y); h[2] = pack2(xa.z); h[3] = pack2(xa.w);
                h[4] = pack2(xb.x); h[5] = pack2(xb.y); h[6] = pack2(xb.z); h[7] = pack2(xb.w);
                const ULL* wp = (const ULL*)(Wc + kk * 514 + ii * 64 + oh * 8);
#pragma unroll
                for (int p = 0; p < 4; p++) {
                    ULL wv = wp[p];
                    fma2(acc[0][p], h[0], wv); fma2(acc[1][p], h[1], wv);
                    fma2(acc[2][p], h[2], wv); fma2(acc[3][p], h[3], wv);
                    fma2(acc[4][p], h[4], wv); fma2(acc[5][p], h[5], wv);
                    fma2(acc[6][p], h[6], wv); fma2(acc[7][p], h[7], wv);
                }
            }
            buf ^= 1;
        }

        // store Mn chunk (conflict-free: bank-pair = kk + 4*oh per warp)
#pragma unroll
        for (int a = 0; a < 8; a++) {
            ULL* mp = (ULL*)(Mns + (q * 8 + a) * MNS + kk * MKS + oh * 8);
#pragma unroll
            for (int p = 0; p < 4; p++) mp[p] = acc[a][p];
        }
        __syncthreads();

        // ---- consume: this chunk's partial messages, committed via atomics ----
        {
            int hb = kc * 8 + (l & 7);
            int pk_n = 0, d_n = 0; float hv_n = 0.f;
            if (w < ntask) {
                pk_n = tasks[w];  d_n = taskD[w];
                hv_n = hE[(pk_n & 0xFFFFFF) * 64 + hb];
            }
            for (int t = w; t < ntask; t += 8) {
                int pk = pk_n, d = d_n; float hv = hv_n;
                int tn = t + 8;
                if (tn < ntask) {
                    if (tn < TCAP) { pk_n = tasks[tn]; d_n = taskD[tn]; }
                    else {
                        int e2 = d_elist[csr0 + tn];
                        pk_n = ((srcp[e2] - nb0) << 24) | e2;
                        d_n = dstp[e2];
                    }
                    hv_n = hE[(pk_n & 0xFFFFFF) * 64 + hb];
                }
                int ln = pk >> 24;
                ULL s2 = 0ull;
                const float* mp = Mns + ln * MNS + o2;
#pragma unroll
                for (int k = 0; k < 8; k++) {
                    float hk = __shfl_sync(0xFFFFFFFFu, hv, k);
                    fma2(s2, pack2(hk), *(const ULL*)(mp + k * MKS));
                }
                float a0, a1; unpack2(s2, a0, a1);
                if (kc == 0) {
                    a0 += __ldg(&bno[(nb0 + ln) * 64 + o2]);
                    a1 += __ldg(&bno[(nb0 + ln) * 64 + o2 + 1]);
                }
                atomicAdd(&agg[d * 64 + o2], a0);
                atomicAdd(&agg[d * 64 + o2 + 1], a1);
            }
        }
    }
}

// ---------------- node update 1 ----------------
__global__ void node_update1(const float* __restrict__ x,
                             const float* __restrict__ root1,
                             const float* __restrict__ bias1) {
    __shared__ float r1[512], b1s[64], xs[4][8], dn[4];
    int tid = threadIdx.x;
    r1[tid] = root1[tid];
    r1[tid + 256] = root1[tid + 256];
    if (tid < 64) b1s[tid] = bias1[tid];
    int n0 = blockIdx.x * 4;
    if (tid < 32) {
        int ln = tid >> 3, j = tid & 7;
        int n = n0 + ln;
        xs[ln][j] = (n < N_NODES) ? x[n * 8 + j] : 0.f;
    }
    if (tid < 4) {
        int n = n0 + tid;
        dn[tid] = (n < N_NODES) ? fmaxf(d_deg[n], 1.f) : 1.f;
    }
    __syncthreads();
    int c = tid & 63, ln = tid >> 6, n = n0 + ln;
    if (n < N_NODES) {
        float s = d_agg1[n * 64 + c] / dn[ln] + b1s[c];
#pragma unroll
        for (int j = 0; j < 8; j++) s += xs[ln][j] * r1[j * 64 + c];
        d_h1[n * 64 + c] = fmaxf(s, 0.f);
    }
}

// ---------------- node update 2 + column sums for mean pool ----------------
__global__ void node_update2(const float* __restrict__ root2,
                             const float* __restrict__ bias2) {
    __shared__ float h1s[64 * 65];
    __shared__ float r2s[64 * 64];
    __shared__ float b2s[64];
    __shared__ float dn[64];
    __shared__ float colpart[4 * 64];
    int tid = threadIdx.x;
    int n0 = blockIdx.x * 64;
    for (int idx = tid; idx < 64 * 64; idx += 256) r2s[idx] = root2[idx];
    for (int idx = tid; idx < 64 * 64; idx += 256) {
        int ln = idx >> 6, kk = idx & 63;
        int n = n0 + ln;
        h1s[ln * 65 + kk] = (n < N_NODES) ? d_h1[n * 64 + kk] : 0.f;
    }
    if (tid < 64) {
        b2s[tid] = bias2[tid];
        int n = n0 + tid;
        dn[tid] = (n < N_NODES) ? fmaxf(d_deg[n], 1.f) : 1.f;
    }
    __syncthreads();
    int c = tid & 63, ng = tid >> 6;
    float csum = 0.f;
    for (int j = 0; j < 16; j++) {
        int ln = ng + 4 * j;
        int n = n0 + ln;
        if (n < N_NODES) {
            float s = d_agg2[n * 64 + c] / dn[ln] + b2s[c];
#pragma unroll 8
            for (int kk = 0; kk < 64; kk++) s += h1s[ln * 65 + kk] * r2s[kk * 64 + c];
            csum += fmaxf(s, 0.f);
        }
    }
    colpart[ng * 64 + c] = csum;
    __syncthreads();
    if (tid < 64) {
        float t = colpart[tid] + colpart[64 + tid] + colpart[128 + tid] + colpart[192 + tid];
        atomicAdd(&d_colsum[tid], t);
    }
}

// ---------------- g vector ----------------
__global__ void g_kernel(const float* __restrict__ projW, const float* __restrict__ projb) {
    __shared__ float cs[64];
    int tid = threadIdx.x;
    cs[tid] = d_colsum[tid] * (1.f / (float)N_NODES);
    __syncthreads();
    float s = projb[tid];
    for (int c = 0; c < 64; c++) s += cs[c] * projW[c * 64 + tid];
    d_g[tid] = s;
}

// ---------------- MLP layer 1 (split-K, f32x2) ----------------
__global__ void mlp1_main(const float* __restrict__ a, const float* __restrict__ mW1) {
    __shared__ __align__(16) float aT[64 * 36];
    __shared__ __align__(16) float Wt[64 * 132];
    int tid = threadIdx.x;
    int m0 = blockIdx.x * 32;
    int ks = blockIdx.y * 313;
    int ke = min(N_ACT, ks + 313);
    int tj = tid & 31, tb = tid >> 5;
    int j0 = tj * 4, b0 = tb * 4;
    ULL acc2[4][2];
#pragma unroll
    for (int p = 0; p < 4; p++) { acc2[p][0] = 0ull; acc2[p][1] = 0ull; }

    for (int kkb = ks; kkb < ke; kkb += 64) {
        int klen = ke - kkb;
        __syncthreads();
        for (int idx = tid; idx < 2048; idx += 256) {
            int b = idx >> 6, k = idx & 63;
            aT[k * 36 + b] = (k < klen) ? a[(m0 + b) * N_ACT + kkb + k] : 0.f;
        }
        for (int idx = tid; idx < 8192; idx += 256) {
            int k = idx >> 7, j = idx & 127;
            Wt[k * 132 + j] = (k < klen) ? mW1[(kkb + k) * 128 + j] : 0.f;
        }
        __syncthreads();
#pragma unroll 8
        for (int k = 0; k < 64; k++) {
            float4 av = *(const float4*)&aT[k * 36 + b0];
            const ULL* wp = (const ULL*)&Wt[k * 132 + j0];
            ULL w0 = wp[0], w1 = wp[1];
            ULL a0 = pack2(av.x), a1 = pack2(av.y);
            ULL a2 = pack2(av.z), a3 = pack2(av.w);
            fma2(acc2[0][0], a0, w0); fma2(acc2[0][1], a0, w1);
            fma2(acc2[1][0], a1, w0); fma2(acc2[1][1], a1, w1);
            fma2(acc2[2][0], a2, w0); fma2(acc2[2][1], a2, w1);
            fma2(acc2[3][0], a3, w0); fma2(acc2[3][1], a3, w1);
        }
    }
#pragma unroll
    for (int p = 0; p < 4; p++) {
        float v0, v1, v2, v3;
        unpack2(acc2[p][0], v0, v1);
        unpack2(acc2[p][1], v2, v3);
        float* yp = &d_y1[(m0 + b0 + p) * 128 + j0];
        atomicAdd(yp + 0, v0);
        atomicAdd(yp + 1, v1);
        atomicAdd(yp + 2, v2);
        atomicAdd(yp + 3, v3);
    }
}

__global__ void mlp1_finish(const float* __restrict__ mW1, const float* __restrict__ mb1) {
    __shared__ float gs[64];
    int tid = threadIdx.x;
    if (tid < 64) gs[tid] = d_g[tid];
    __syncthreads();
    int idx = blockIdx.x * 256 + tid;
    int j = idx & 127;
    float s = d_y1[idx] + mb1[j];
    for (int c = 0; c < 64; c++) s += gs[c] * mW1[(N_ACT + c) * 128 + j];
    d_z1[idx] = fmaxf(s, 0.f);
}

__global__ void mlp2_kernel(const float* __restrict__ mW2, const float* __restrict__ mb2) {
    __shared__ float zs[2][128];
    int tid = threadIdx.x;
    int b0 = blockIdx.x * 2;
    zs[tid >> 7][tid & 127] = d_z1[b0 * 128 + tid];
    __syncthreads();
    int lb = tid >> 7, j = tid & 127;
    float s = mb2[j];
#pragma unroll 4
    for (int k = 0; k < 128; k++) s += zs[lb][k] * mW2[k * 128 + j];
    d_z2[(b0 + lb) * 128 + j] = fmaxf(s, 0.f);
}

__global__ void mlp3_kernel(const float* __restrict__ mW3, const float* __restrict__ mb3,
                            float* __restrict__ out) {
    __shared__ float w3[128];
    int tid = threadIdx.x;
    if (tid < 128) w3[tid] = mW3[tid];
    __syncthreads();
    float s = mb3[0];
    for (int j = 0; j < 128; j++) s += d_z2[tid * 128 + j] * w3[j];
    out[tid] = s;
}

// ---------------- launcher ----------------
extern "C" void kernel_launch(void* const* d_in, const int* in_sizes, int n_in,
                              void* d_out, int out_size) {
    const float* x     = (const float*)d_in[0];
    const int*   ei    = (const int*)  d_in[1];
    const float* ea    = (const float*)d_in[2];
    const float* a     = (const float*)d_in[3];
    const float* e1W1  = (const float*)d_in[4];
    const float* e1b1  = (const float*)d_in[5];
    const float* e1W2  = (const float*)d_in[6];
    const float* e1b2  = (const float*)d_in[7];
    const float* root1 = (const float*)d_in[8];
    const float* bias1 = (const float*)d_in[9];
    const float* e2W1  = (const float*)d_in[10];
    const float* e2b1  = (const float*)d_in[11];
    const float* e2W2  = (const float*)d_in[12];
    const float* e2b2  = (const float*)d_in[13];
    const float* root2 = (const float*)d_in[14];
    const float* bias2 = (const float*)d_in[15];
    const float* projW = (const float*)d_in[16];
    const float* projb = (const float*)d_in[17];
    const float* mW1   = (const float*)d_in[18];
    const float* mb1   = (const float*)d_in[19];
    const float* mW2   = (const float*)d_in[20];
    const float* mb2   = (const float*)d_in[21];
    const float* mW3   = (const float*)d_in[22];
    const float* mb3   = (const float*)d_in[23];
    float* out = (float*)d_out;

    // smem (floats): xsT + Wss(2*4112) + Mns(32*528) + tasks + taskD + 2
    const int sbase = (2 * WBUF + NT * 528 + TCAP + TCAP + 2);
    const int s8  = (8  * 36 + sbase) * 4;   // ~103.2 KB
    const int s64 = (64 * 36 + sbase) * 4;   // ~111.2 KB -> 2 blocks/SM
    cudaFuncSetAttribute(nnconv_kernel<8>,  cudaFuncAttributeMaxDynamicSharedMemorySize, s8);
    cudaFuncSetAttribute(nnconv_kernel<64>, cudaFuncAttributeMaxDynamicSharedMemorySize, s64);

    const int NB = (N_NODES + NT - 1) / NT;   // 625

    zero_kernel<<<512, 256>>>();                                           // 0
    edge_feat_kernel<<<(N_EDGES + 15) / 16, 256>>>(ea, ei, e1W1, e1b1,
                                                   e2W1, e2b1);            // 1
    scanscatter_kernel<<<1, 1024>>>(ei);                                   // 2
    nnconv_kernel<8><<<NB, NTHR, s8>>>(x, e1W2, e1b2, ei);                 // 3 (profiled)
    node_update1<<<(N_NODES + 3) / 4, 256>>>(x, root1, bias1);             // 4
    nnconv_kernel<64><<<NB, NTHR, s64>>>(x, e2W2, e2b2, ei);               // 5
    node_update2<<<(N_NODES + 63) / 64, 256>>>(root2, bias2);              // 6
    g_kernel<<<1, 64>>>(projW, projb);                                     // 7
    mlp1_main<<<dim3(8, 64), 256>>>(a, mW1);                               // 8
    mlp1_finish<<<128, 256>>>(mW1, mb1);                                   // 9
    mlp2_kernel<<<128, 256>>>(mW2, mb2);                                   // 10
    mlp3_kernel<<<1, 256>>>(mW3, mb3, out);                                // 11
}

// round 14
// speedup vs baseline: 1.3615x; 1.0169x over previous
#include <cuda_runtime.h>

#define N_NODES 20000
#define N_EDGES 60000
#define NODE_IN 8
#define HID     64
#define BATCH   256
#define MLP_H   128
#define N_ACT   20000

#define NT    32     // nodes per block in nnconv
#define NTHR  256    // threads per nnconv block
#define TCAP  192    // edge-task list capacity per block
#define WBUF  4112   // 8*514 floats per Wss buffer

typedef unsigned long long ULL;

// ---------------- device scratch ----------------
__device__ float d_h1e[N_EDGES * HID];
__device__ float d_h2e[N_EDGES * HID];
__device__ float d_deg[N_NODES];
__device__ float d_agg1[N_NODES * HID];
__device__ float d_h1[N_NODES * HID];
__device__ float d_agg2[N_NODES * HID];
__device__ float d_colsum[HID];
__device__ float d_g[HID];
__device__ float d_y1[BATCH * MLP_H];
__device__ float d_z1[BATCH * MLP_H];
__device__ float d_z2[BATCH * MLP_H];
__device__ float d_bn1[N_NODES * HID];
__device__ float d_bn2[N_NODES * HID];
// CSR by src
__device__ int d_srccnt[N_NODES];
__device__ int d_fill[N_NODES];
__device__ int d_srcptr[N_NODES + 1];
__device__ int d_elist[N_EDGES];

// f32x2 packed helpers
__device__ __forceinline__ ULL pack2(float v) {
    ULL r;
    asm("mov.b64 %0, {%1, %1};" : "=l"(r) : "f"(v));
    return r;
}
__device__ __forceinline__ void fma2(ULL& acc, ULL a, ULL b) {
    asm("fma.rn.f32x2 %0, %1, %2, %0;" : "+l"(acc) : "l"(a), "l"(b));
}
__device__ __forceinline__ void unpack2(ULL v, float& lo, float& hi) {
    asm("mov.b64 {%0, %1}, %2;" : "=f"(lo), "=f"(hi) : "l"(v));
}
// vector reduction: agg[0..3] += {a,b,c,d}
__device__ __forceinline__ void red4(float* ptr, float a, float b, float c, float d) {
    asm volatile("red.global.add.v4.f32 [%0], {%1, %2, %3, %4};"
                 :: "l"(ptr), "f"(a), "f"(b), "f"(c), "f"(d) : "memory");
}
// cp.async helpers
__device__ __forceinline__ void cpa8(unsigned dst, const void* src) {
    asm volatile("cp.async.ca.shared.global [%0], [%1], 8;" :: "r"(dst), "l"(src) : "memory");
}
__device__ __forceinline__ void cpa_commit() {
    asm volatile("cp.async.commit_group;" ::: "memory");
}
template<int N> __device__ __forceinline__ void cpa_wait() {
    asm volatile("cp.async.wait_group %0;" :: "n"(N) : "memory");
}

// ---------------- zero scratch ----------------
__global__ void zero_kernel() {
    int i  = blockIdx.x * blockDim.x + threadIdx.x;
    int gs = gridDim.x * blockDim.x;
    for (int j = i; j < N_NODES * HID; j += gs) { d_agg1[j] = 0.f; d_agg2[j] = 0.f; }
    for (int j = i; j < N_NODES; j += gs) { d_deg[j] = 0.f; d_srccnt[j] = 0; d_fill[j] = 0; }
    for (int j = i; j < BATCH * MLP_H; j += gs) d_y1[j] = 0.f;
    if (i < HID) d_colsum[i] = 0.f;
}

// ---------------- edge feature MLPs + degree counts ----------------
__global__ void edge_feat_kernel(const float* __restrict__ edge_attr,
                                 const int*   __restrict__ edge_index,
                                 const float* __restrict__ W1a, const float* __restrict__ b1a,
                                 const float* __restrict__ W1b, const float* __restrict__ b1b) {
    __shared__ float wa[256], wb[256], ba[64], bb[64], ea[16][4];
    int tid = threadIdx.x;
    wa[tid] = W1a[tid];
    wb[tid] = W1b[tid];
    if (tid < 64) { ba[tid] = b1a[tid]; bb[tid] = b1b[tid]; }
    int e0 = blockIdx.x * 16;
    if (tid < 64) {
        int le = tid >> 2, j = tid & 3;
        int e = e0 + le;
        ea[le][j] = (e < N_EDGES) ? edge_attr[e * 4 + j] : 0.f;
    }
    __syncthreads();
    int c = tid & 63;
#pragma unroll
    for (int ch = 0; ch < 4; ch++) {
        int le = (tid >> 6) + ch * 4;
        int e = e0 + le;
        if (e < N_EDGES) {
            float s1 = ba[c], s2 = bb[c];
#pragma unroll
            for (int j = 0; j < 4; j++) {
                s1 += ea[le][j] * wa[j * 64 + c];
                s2 += ea[le][j] * wb[j * 64 + c];
            }
            d_h1e[e * 64 + c] = fmaxf(s1, 0.f);
            d_h2e[e * 64 + c] = fmaxf(s2, 0.f);
            if (c == 0) atomicAdd(&d_deg[edge_index[N_EDGES + e]], 1.f);
            if (c == 1) atomicAdd(&d_srccnt[edge_index[e]], 1);
        }
    }
}

// ---------------- fused exclusive scan + CSR scatter (single block) ----------------
__global__ void scanscatter_kernel(const int* __restrict__ edge_index) {
    __shared__ int part[1024];
    int tid = threadIdx.x;
    const int CH = (N_NODES + 1023) / 1024;   // 20
    int base = tid * CH;
    int s = 0;
    for (int j = 0; j < CH; j++) {
        int idx = base + j;
        if (idx < N_NODES) s += d_srccnt[idx];
    }
    part[tid] = s;
    __syncthreads();
    for (int off = 1; off < 1024; off <<= 1) {
        int v = (tid >= off) ? part[tid - off] : 0;
        __syncthreads();
        part[tid] += v;
        __syncthreads();
    }
    int run = (tid > 0) ? part[tid - 1] : 0;
    for (int j = 0; j < CH; j++) {
        int idx = base + j;
        if (idx < N_NODES) { d_srcptr[idx] = run; run += d_srccnt[idx]; }
    }
    if (tid == 1023) d_srcptr[N_NODES] = run;
    __syncthreads();
    // scatter edges into CSR lists
    for (int e = tid; e < N_EDGES; e += 1024) {
        int sv = edge_index[e];
        int pos = d_srcptr[sv] + atomicAdd(&d_fill[sv], 1);
        d_elist[pos] = e;
    }
}

// ---------------- W2 tile prefetch (cp.async, 8B) ----------------
template<int IDIM>
__device__ __forceinline__ void stage_w2(const float* __restrict__ W2,
                                         unsigned wss_smem, int kc, int is, int tid) {
    constexpr int WROW = IDIM * 64;
#pragma unroll
    for (int j = 0; j < 8; j++) {
        int p2 = tid + j * NTHR;          // pair index 0..2047
        int o2 = p2 & 31;
        int ks = (p2 >> 5) & 7;
        int ii = p2 >> 8;
        const float* src = W2 + (kc * 8 + ks) * WROW + (is * 8 + ii) * 64 + o2 * 2;
        unsigned dst = wss_smem + (unsigned)((ks * 514 + ii * 64 + o2 * 2) * 4);
        cpa8(dst, src);
    }
}

// ---------------- NNConv: per-NODE weight GEMM (f32x2), k-chunked,
//                  half-warp-per-task consume with v4 reductions ----
template<int IDIM>
__launch_bounds__(NTHR, 2)
__global__ void nnconv_kernel(const float* __restrict__ xin_param,
                              const float* __restrict__ W2,
                              const float* __restrict__ b2,
                              const int*   __restrict__ edge_index) {
    const float* xin = (IDIM == 8) ? xin_param : d_h1;
    const float* hE  = (IDIM == 8) ? d_h1e : d_h2e;
    float*       agg = (IDIM == 8) ? d_agg1 : d_agg2;
    float*       bno = (IDIM == 8) ? d_bn1 : d_bn2;
    const int*   srcp = edge_index;
    const int*   dstp = edge_index + N_EDGES;

    constexpr int IS   = IDIM / 8;   // i-stages per k-chunk
    constexpr int NST  = 8 * IS;     // total stages
    constexpr int XR   = 36;         // xsT row stride
    constexpr int MKS  = 66;         // Mns per-k stride
    constexpr int MNS  = 8 * MKS;    // 528 per node

    extern __shared__ float sm[];
    float* xsT  = sm;                         // [IDIM][XR]   xsT[i][n]
    float* Wss  = xsT + IDIM * XR;            // [2][8][514]  double-buffered W2 tile
    float* Mns  = Wss + 2 * WBUF;             // [NT][8k][66] (head reused for b2)
    int*  tasks = (int*)(Mns + NT * MNS);     // [TCAP]  (ln<<24)|e
    int*  taskD = tasks + TCAP;               // [TCAP]  dst
    int*  sNT   = taskD + TCAP;               // [2]: ntask, csr0

    int tid = threadIdx.x;
    int nb0 = blockIdx.x * NT;
    unsigned wss_base = (unsigned)__cvta_generic_to_shared(Wss);

    // kick off pipeline: stage 0 into buffer 0 (overlaps prologue)
    stage_w2<IDIM>(W2, wss_base, 0, 0, tid);
    cpa_commit();

    // transposed node features
    for (int idx = tid; idx < NT * IDIM; idx += NTHR) {
        int i = idx % IDIM, n = idx / IDIM;
        int gn = nb0 + n;
        xsT[i * XR + n] = (gn < N_NODES) ? xin[gn * IDIM + i] : 0.f;
    }
    if (tid == 0) {
        int c0 = d_srcptr[nb0];
        int hi = nb0 + NT; if (hi > N_NODES) hi = N_NODES;
        sNT[0] = d_srcptr[hi] - c0;
        sNT[1] = c0;
    }
    // stage b2 (flat) into Mns head (free until first Mn store)
    for (int idx = tid; idx < IDIM * 64; idx += NTHR) Mns[idx] = b2[idx];
    __syncthreads();
    int ntask = sNT[0];
    int csr0  = sNT[1];
    // task lists
    for (int t = tid; t < ntask && t < TCAP; t += NTHR) {
        int e = d_elist[csr0 + t];
        tasks[t] = ((srcp[e] - nb0) << 24) | e;
        taskD[t] = dstp[e];
    }
    // bn[n][o] = sum_i xsT[i][n] * b2[i*64+o]  -> global scratch (freed smem)
    for (int idx = tid; idx < NT * 64; idx += NTHR) {
        int o = idx & 63, n = idx >> 6;
        float s = 0.f;
#pragma unroll 8
        for (int i = 0; i < IDIM; i++) s += xsT[i * XR + n] * Mns[i * 64 + o];
        int gn = nb0 + n;
        if (gn < N_NODES) bno[gn * 64 + o] = s;
    }

    int q  = tid >> 6;       // node oct (warp-uniform): nodes q*8..q*8+7
    int rr = tid & 63;
    int kk = rr >> 3;        // k within chunk
    int oh = rr & 7;         // o octet
    int w = tid >> 5, l = tid & 31;
    int half = l >> 4, hl = l & 15;   // consume role: half-warp, lane-in-half
    int o4 = 4 * hl;

    int buf = 0;
    for (int kc = 0; kc < 8; kc++) {
        ULL acc[8][4];
#pragma unroll
        for (int a = 0; a < 8; a++)
#pragma unroll
            for (int p = 0; p < 4; p++) acc[a][p] = 0ull;

        for (int is = 0; is < IS; is++) {
            __syncthreads();   // buf^1 readers done / prev-kc Mns readers done
            int sn = kc * IS + is + 1;
            if (sn < NST) {
                stage_w2<IDIM>(W2, wss_base + (unsigned)((buf ^ 1) * WBUF * 4),
                               sn / IS, sn % IS, tid);
                cpa_commit();
                cpa_wait<1>();   // current stage's copy complete; next may fly
            } else {
                cpa_wait<0>();
            }
            __syncthreads();     // current buffer visible to all

            const float* Wc = Wss + buf * WBUF;
#pragma unroll
            for (int ii = 0; ii < 8; ii++) {
                int i = is * 8 + ii;
                const float4* xr = (const float4*)(xsT + i * XR + q * 8);
                float4 xa = xr[0], xb = xr[1];
                ULL h[8];
                h[0] = pack2(xa.x); h[1] = pack2(xa.y); h[2] = pack2(xa.z); h[3] = pack2(xa.w);
                h[4] = pack2(xb.x); h[5] = pack2(xb.y); h[6] = pack2(xb.z); h[7] = pack2(xb.w);
                const ULL* wp = (const ULL*)(Wc + kk * 514 + ii * 64 + oh * 8);
#pragma unroll
                for (int p = 0; p < 4; p++) {
                    ULL wv = wp[p];
                    fma2(acc[0][p], h[0], wv); fma2(acc[1][p], h[1], wv);
                    fma2(acc[2][p], h[2], wv); fma2(acc[3][p], h[3], wv);
                    fma2(acc[4][p], h[4], wv); fma2(acc[5][p], h[5], wv);
                    fma2(acc[6][p], h[6], wv); fma2(acc[7][p], h[7], wv);
                }
            }
            buf ^= 1;
        }

        // store Mn chunk (conflict-free: bank-pair = kk + 4*oh per warp)
#pragma unroll
        for (int a = 0; a < 8; a++) {
            ULL* mp = (ULL*)(Mns + (q * 8 + a) * MNS + kk * MKS + oh * 8);
#pragma unroll
            for (int p = 0; p < 4; p++) mp[p] = acc[a][p];
        }
        __syncthreads();

        // ---- consume: 2 tasks per warp (one per half-warp), v4 reductions ----
        {
            int hb = kc * 8 + (hl & 7);
            int pk_n = 0, d_n = 0; float hv_n = 0.f;
            {
                int tt = 2 * w + half;
                if (tt < ntask) {
                    if (tt < TCAP) { pk_n = tasks[tt]; d_n = taskD[tt]; }
                    else {
                        int e2 = d_elist[csr0 + tt];
                        pk_n = ((srcp[e2] - nb0) << 24) | e2;
                        d_n = dstp[e2];
                    }
                    hv_n = hE[(pk_n & 0xFFFFFF) * 64 + hb];
                }
            }
            for (int t = 2 * w; t < ntask; t += 16) {
                int pk = pk_n, d = d_n; float hv = hv_n;
                bool valid = (t + half) < ntask;
                int tn = t + 16 + half;
                if (tn < ntask) {
                    if (tn < TCAP) { pk_n = tasks[tn]; d_n = taskD[tn]; }
                    else {
                        int e2 = d_elist[csr0 + tn];
                        pk_n = ((srcp[e2] - nb0) << 24) | e2;
                        d_n = dstp[e2];
                    }
                    hv_n = hE[(pk_n & 0xFFFFFF) * 64 + hb];
                }
                int ln = pk >> 24;
                const float* mp = Mns + ln * MNS + o4;
                ULL a01 = 0ull, a23 = 0ull;   // two independent chains
#pragma unroll
                for (int k = 0; k < 8; k++) {
                    float hk = __shfl_sync(0xFFFFFFFFu, hv, (half << 4) + k);
                    ULL hk2 = pack2(hk);
                    fma2(a01, hk2, *(const ULL*)(mp + k * MKS));
                    fma2(a23, hk2, *(const ULL*)(mp + k * MKS + 2));
                }
                if (valid) {
                    float v0, v1, v2, v3;
                    unpack2(a01, v0, v1);
                    unpack2(a23, v2, v3);
                    if (kc == 0) {
                        const float4 bv = *(const float4*)&bno[(nb0 + ln) * 64 + o4];
                        v0 += bv.x; v1 += bv.y; v2 += bv.z; v3 += bv.w;
                    }
                    red4(&agg[d * 64 + o4], v0, v1, v2, v3);
                }
            }
        }
    }
}

// ---------------- node update 1 ----------------
__global__ void node_update1(const float* __restrict__ x,
                             const float* __restrict__ root1,
                             const float* __restrict__ bias1) {
    __shared__ float r1[512], b1s[64], xs[4][8], dn[4];
    int tid = threadIdx.x;
    r1[tid] = root1[tid];
    r1[tid + 256] = root1[tid + 256];
    if (tid < 64) b1s[tid] = bias1[tid];
    int n0 = blockIdx.x * 4;
    if (tid < 32) {
        int ln = tid >> 3, j = tid & 7;
        int n = n0 + ln;
        xs[ln][j] = (n < N_NODES) ? x[n * 8 + j] : 0.f;
    }
    if (tid < 4) {
        int n = n0 + tid;
        dn[tid] = (n < N_NODES) ? fmaxf(d_deg[n], 1.f) : 1.f;
    }
    __syncthreads();
    int c = tid & 63, ln = tid >> 6, n = n0 + ln;
    if (n < N_NODES) {
        float s = d_agg1[n * 64 + c] / dn[ln] + b1s[c];
#pragma unroll
        for (int j = 0; j < 8; j++) s += xs[ln][j] * r1[j * 64 + c];
        d_h1[n * 64 + c] = fmaxf(s, 0.f);
    }
}

// ---------------- node update 2 + column sums for mean pool ----------------
__global__ void node_update2(const float* __restrict__ root2,
                             const float* __restrict__ bias2) {
    __shared__ float h1s[64 * 65];
    __shared__ float r2s[64 * 64];
    __shared__ float b2s[64];
    __shared__ float dn[64];
    __shared__ float colpart[4 * 64];
    int tid = threadIdx.x;
    int n0 = blockIdx.x * 64;
    for (int idx = tid; idx < 64 * 64; idx += 256) r2s[idx] = root2[idx];
    for (int idx = tid; idx < 64 * 64; idx += 256) {
        int ln = idx >> 6, kk = idx & 63;
        int n = n0 + ln;
        h1s[ln * 65 + kk] = (n < N_NODES) ? d_h1[n * 64 + kk] : 0.f;
    }
    if (tid < 64) {
        b2s[tid] = bias2[tid];
        int n = n0 + tid;
        dn[tid] = (n < N_NODES) ? fmaxf(d_deg[n], 1.f) : 1.f;
    }
    __syncthreads();
    int c = tid & 63, ng = tid >> 6;
    float csum = 0.f;
    for (int j = 0; j < 16; j++) {
        int ln = ng + 4 * j;
        int n = n0 + ln;
        if (n < N_NODES) {
            float s = d_agg2[n * 64 + c] / dn[ln] + b2s[c];
#pragma unroll 8
            for (int kk = 0; kk < 64; kk++) s += h1s[ln * 65 + kk] * r2s[kk * 64 + c];
            csum += fmaxf(s, 0.f);
        }
    }
    colpart[ng * 64 + c] = csum;
    __syncthreads();
    if (tid < 64) {
        float t = colpart[tid] + colpart[64 + tid] + colpart[128 + tid] + colpart[192 + tid];
        atomicAdd(&d_colsum[tid], t);
    }
}

// ---------------- g vector ----------------
__global__ void g_kernel(const float* __restrict__ projW, const float* __restrict__ projb) {
    __shared__ float cs[64];
    int tid = threadIdx.x;
    cs[tid] = d_colsum[tid] * (1.f / (float)N_NODES);
    __syncthreads();
    float s = projb[tid];
    for (int c = 0; c < 64; c++) s += cs[c] * projW[c * 64 + tid];
    d_g[tid] = s;
}

// ---------------- MLP layer 1 (split-K, f32x2) ----------------
__global__ void mlp1_main(const float* __restrict__ a, const float* __restrict__ mW1) {
    __shared__ __align__(16) float aT[64 * 36];
    __shared__ __align__(16) float Wt[64 * 132];
    int tid = threadIdx.x;
    int m0 = blockIdx.x * 32;
    int ks = blockIdx.y * 313;
    int ke = min(N_ACT, ks + 313);
    int tj = tid & 31, tb = tid >> 5;
    int j0 = tj * 4, b0 = tb * 4;
    ULL acc2[4][2];
#pragma unroll
    for (int p = 0; p < 4; p++) { acc2[p][0] = 0ull; acc2[p][1] = 0ull; }

    for (int kkb = ks; kkb < ke; kkb += 64) {
        int klen = ke - kkb;
        __syncthreads();
        for (int idx = tid; idx < 2048; idx += 256) {
            int b = idx >> 6, k = idx & 63;
            aT[k * 36 + b] = (k < klen) ? a[(m0 + b) * N_ACT + kkb + k] : 0.f;
        }
        for (int idx = tid; idx < 8192; idx += 256) {
            int k = idx >> 7, j = idx & 127;
            Wt[k * 132 + j] = (k < klen) ? mW1[(kkb + k) * 128 + j] : 0.f;
        }
        __syncthreads();
#pragma unroll 8
        for (int k = 0; k < 64; k++) {
            float4 av = *(const float4*)&aT[k * 36 + b0];
            const ULL* wp = (const ULL*)&Wt[k * 132 + j0];
            ULL w0 = wp[0], w1 = wp[1];
            ULL a0 = pack2(av.x), a1 = pack2(av.y);
            ULL a2 = pack2(av.z), a3 = pack2(av.w);
            fma2(acc2[0][0], a0, w0); fma2(acc2[0][1], a0, w1);
            fma2(acc2[1][0], a1, w0); fma2(acc2[1][1], a1, w1);
            fma2(acc2[2][0], a2, w0); fma2(acc2[2][1], a2, w1);
            fma2(acc2[3][0], a3, w0); fma2(acc2[3][1], a3, w1);
        }
    }
#pragma unroll
    for (int p = 0; p < 4; p++) {
        float v0, v1, v2, v3;
        unpack2(acc2[p][0], v0, v1);
        unpack2(acc2[p][1], v2, v3);
        red4(&d_y1[(m0 + b0 + p) * 128 + j0], v0, v1, v2, v3);
    }
}

__global__ void mlp1_finish(const float* __restrict__ mW1, const float* __restrict__ mb1) {
    __shared__ float gs[64];
    int tid = threadIdx.x;
    if (tid < 64) gs[tid] = d_g[tid];
    __syncthreads();
    int idx = blockIdx.x * 256 + tid;
    int j = idx & 127;
    float s = d_y1[idx] + mb1[j];
    for (int c = 0; c < 64; c++) s += gs[c] * mW1[(N_ACT + c) * 128 + j];
    d_z1[idx] = fmaxf(s, 0.f);
}

__global__ void mlp2_kernel(const float* __restrict__ mW2, const float* __restrict__ mb2) {
    __shared__ float zs[2][128];
    int tid = threadIdx.x;
    int b0 = blockIdx.x * 2;
    zs[tid >> 7][tid & 127] = d_z1[b0 * 128 + tid];
    __syncthreads();
    int lb = tid >> 7, j = tid & 127;
    float s = mb2[j];
#pragma unroll 4
    for (int k = 0; k < 128; k++) s += zs[lb][k] * mW2[k * 128 + j];
    d_z2[(b0 + lb) * 128 + j] = fmaxf(s, 0.f);
}

__global__ void mlp3_kernel(const float* __restrict__ mW3, const float* __restrict__ mb3,
                            float* __restrict__ out) {
    __shared__ float w3[128];
    int tid = threadIdx.x;
    if (tid < 128) w3[tid] = mW3[tid];
    __syncthreads();
    float s = mb3[0];
    for (int j = 0; j < 128; j++) s += d_z2[tid * 128 + j] * w3[j];
    out[tid] = s;
}

// ---------------- launcher ----------------
extern "C" void kernel_launch(void* const* d_in, const int* in_sizes, int n_in,
                              void* d_out, int out_size) {
    const float* x     = (const float*)d_in[0];
    const int*   ei    = (const int*)  d_in[1];
    const float* ea    = (const float*)d_in[2];
    const float* a     = (const float*)d_in[3];
    const float* e1W1  = (const float*)d_in[4];
    const float* e1b1  = (const float*)d_in[5];
    const float* e1W2  = (const float*)d_in[6];
    const float* e1b2  = (const float*)d_in[7];
    const float* root1 = (const float*)d_in[8];
    const float* bias1 = (const float*)d_in[9];
    const float* e2W1  = (const float*)d_in[10];
    const float* e2b1  = (const float*)d_in[11];
    const float* e2W2  = (const float*)d_in[12];
    const float* e2b2  = (const float*)d_in[13];
    const float* root2 = (const float*)d_in[14];
    const float* bias2 = (const float*)d_in[15];
    const float* projW = (const float*)d_in[16];
    const float* projb = (const float*)d_in[17];
    const float* mW1   = (const float*)d_in[18];
    const float* mb1   = (const float*)d_in[19];
    const float* mW2   = (const float*)d_in[20];
    const float* mb2   = (const float*)d_in[21];
    const float* mW3   = (const float*)d_in[22];
    const float* mb3   = (const float*)d_in[23];
    float* out = (float*)d_out;

    // smem (floats): xsT + Wss(2*4112) + Mns(32*528) + tasks + taskD + 2
    const int sbase = (2 * WBUF + NT * 528 + TCAP + TCAP + 2);
    const int s8  = (8  * 36 + sbase) * 4;   // ~103.2 KB
    const int s64 = (64 * 36 + sbase) * 4;   // ~111.2 KB -> 2 blocks/SM
    cudaFuncSetAttribute(nnconv_kernel<8>,  cudaFuncAttributeMaxDynamicSharedMemorySize, s8);
    cudaFuncSetAttribute(nnconv_kernel<64>, cudaFuncAttributeMaxDynamicSharedMemorySize, s64);

    const int NB = (N_NODES + NT - 1) / NT;   // 625

    zero_kernel<<<512, 256>>>();                                           // 0
    edge_feat_kernel<<<(N_EDGES + 15) / 16, 256>>>(ea, ei, e1W1, e1b1,
                                                   e2W1, e2b1);            // 1
    scanscatter_kernel<<<1, 1024>>>(ei);                                   // 2
    nnconv_kernel<8><<<NB, NTHR, s8>>>(x, e1W2, e1b2, ei);                 // 3 (profiled)
    node_update1<<<(N_NODES + 3) / 4, 256>>>(x, root1, bias1);             // 4
    nnconv_kernel<64><<<NB, NTHR, s64>>>(x, e2W2, e2b2, ei);               // 5
    node_update2<<<(N_NODES + 63) / 64, 256>>>(root2, bias2);              // 6
    g_kernel<<<1, 64>>>(projW, projb);                                     // 7
    mlp1_main<<<dim3(8, 64), 256>>>(a, mW1);                               // 8
    mlp1_finish<<<128, 256>>>(mW1, mb1);                                   // 9
    mlp2_kernel<<<128, 256>>>(mW2, mb2);                                   // 10
    mlp3_kernel<<<1, 256>>>(mW3, mb3, out);                                // 11
}